// round 5
// baseline (speedup 1.0000x reference)
#include <cuda_runtime.h>

// ---------------- static config ----------------
#define NCAM   6
#define FC     128
#define FH     32
#define FW     88
#define NPIX   (FH*FW)          // 2816
#define DLEV   41
#define OC3    170              // 41 depth + 1 opacity + 128 feat
#define OUTC   128
#define G_TOT  (NCAM*NPIX)      // 16896
#define BEV_H  100
#define BEV_W  100
#define P_TOT  (BEV_H*BEV_W)    // 10000

// ---------------- scratch (device globals; no allocation) ----------------
__device__ float g_x1[NCAM*FC*NPIX];        // conv1 out
__device__ float g_x2[NCAM*FC*NPIX];        // conv2 out
__device__ float g_logits[NCAM*OC3*NPIX];   // conv3 out
__device__ float g_colors[G_TOT*OUTC];      // [g][c] transposed features
__device__ float g_gMy[G_TOT], g_gMx[G_TOT];
__device__ float g_gA[G_TOT], g_gB[G_TOT], g_gC[G_TOT];
__device__ float g_gOp[G_TOT], g_gQ[G_TOT];
__device__ float g_cam[NCAM*24];            // comb[9], invPostRot[9], trans[3], posttrans[3]
__device__ float g_sc1[FC], g_sh1[FC], g_sc2[FC], g_sh2[FC];
__device__ int   g_cnt;

// ---------------- setup ----------------
__device__ __forceinline__ void inv3(const float* m, float* o) {
    float a=m[0],b=m[1],c=m[2],d=m[3],e=m[4],f=m[5],g=m[6],h=m[7],i=m[8];
    float A =  (e*i - f*h);
    float B = -(d*i - f*g);
    float C =  (d*h - e*g);
    float det = a*A + b*B + c*C;
    float id = 1.0f/det;
    o[0]=A*id;            o[1]=-(b*i-c*h)*id;  o[2]= (b*f-c*e)*id;
    o[3]=B*id;            o[4]= (a*i-c*g)*id;  o[5]=-(a*f-c*d)*id;
    o[6]=C*id;            o[7]=-(a*h-b*g)*id;  o[8]= (a*e-b*d)*id;
}

__global__ void k_setup(const float* __restrict__ rots, const float* __restrict__ trans,
                        const float* __restrict__ intr, const float* __restrict__ prots,
                        const float* __restrict__ ptrans,
                        const float* __restrict__ c1b, const float* __restrict__ g1,
                        const float* __restrict__ b1,  const float* __restrict__ m1,
                        const float* __restrict__ v1,
                        const float* __restrict__ c2b, const float* __restrict__ g2,
                        const float* __restrict__ b2,  const float* __restrict__ m2,
                        const float* __restrict__ v2) {
    int t = threadIdx.x;
    if (t < NCAM) {
        float iK[9], iPR[9], comb[9];
        inv3(intr + t*9, iK);
        inv3(prots + t*9, iPR);
        const float* R = rots + t*9;
        #pragma unroll
        for (int r = 0; r < 3; r++)
            #pragma unroll
            for (int c = 0; c < 3; c++)
                comb[r*3+c] = R[r*3+0]*iK[0*3+c] + R[r*3+1]*iK[1*3+c] + R[r*3+2]*iK[2*3+c];
        float* o = g_cam + t*24;
        #pragma unroll
        for (int j = 0; j < 9; j++) o[j]   = comb[j];
        #pragma unroll
        for (int j = 0; j < 9; j++) o[9+j] = iPR[j];
        o[18]=trans[t*3+0]; o[19]=trans[t*3+1]; o[20]=trans[t*3+2];
        o[21]=ptrans[t*3+0]; o[22]=ptrans[t*3+1]; o[23]=ptrans[t*3+2];
    }
    if (t < FC) {
        float s1 = g1[t]*rsqrtf(v1[t] + 1e-3f);
        g_sc1[t] = s1;
        g_sh1[t] = (c1b[t] - m1[t])*s1 + b1[t];
        float s2 = g2[t]*rsqrtf(v2[t] + 1e-3f);
        g_sc2[t] = s2;
        g_sh2[t] = (c2b[t] - m2[t])*s2 + b2[t];
    }
    if (t == 0) g_cnt = 0;
}

// ---------------- conv3x3 + BN + ReLU ----------------
// grid (8 h-tiles, 8 oc-tiles, 6 images), block 256.
// thread: oc_l = tid/16 (16 oc per block), s = tid%16 -> row r = s/4 (4 rows), col run = (s%3?)*22
__global__ void k_conv3x3(const float* __restrict__ feats,
                          const float* __restrict__ wgt,
                          int which) {
    __shared__ float sIn[6][90];
    __shared__ float sW[16][9];
    const float* inp = which ? g_x1 : feats;
    float*       out = which ? g_x2 : g_x1;
    const float* sc  = which ? g_sc2 : g_sc1;
    const float* sh  = which ? g_sh2 : g_sh1;

    int h0  = blockIdx.x * 4;
    int oc0 = blockIdx.y * 16;
    int n   = blockIdx.z;
    int tid = threadIdx.x;
    int oc_l = tid >> 4;
    int s    = tid & 15;
    int r    = s >> 2;
    int c0   = (s & 3) * 22;

    float acc[22];
    #pragma unroll
    for (int j = 0; j < 22; j++) acc[j] = 0.0f;

    for (int ic = 0; ic < FC; ic++) {
        __syncthreads();
        for (int idx = tid; idx < 540; idx += 256) {
            int rr = idx / 90, cc = idx - rr*90;
            int gh = h0 - 1 + rr, gw = cc - 1;
            float v = 0.0f;
            if ((unsigned)gh < FH && (unsigned)gw < FW)
                v = inp[((n*FC + ic)*FH + gh)*FW + gw];
            sIn[rr][cc] = v;
        }
        if (tid < 144) {
            int ocl = tid / 9, kk = tid - ocl*9;
            sW[ocl][kk] = wgt[((oc0 + ocl)*FC + ic)*9 + kk];
        }
        __syncthreads();

        float wv[9];
        #pragma unroll
        for (int t2 = 0; t2 < 9; t2++) wv[t2] = sW[oc_l][t2];
        #pragma unroll
        for (int kh = 0; kh < 3; kh++) {
            const float* rp = &sIn[r + kh][c0];
            float ld[24];
            #pragma unroll
            for (int j = 0; j < 24; j++) ld[j] = rp[j];
            #pragma unroll
            for (int j = 0; j < 22; j++)
                acc[j] = fmaf(wv[kh*3+0], ld[j],
                          fmaf(wv[kh*3+1], ld[j+1],
                           fmaf(wv[kh*3+2], ld[j+2], acc[j])));
        }
    }

    int oc = oc0 + oc_l;
    float scv = sc[oc], shv = sh[oc];
    float* op_ = out + ((n*FC + oc)*FH + (h0 + r))*FW + c0;
    #pragma unroll
    for (int j = 0; j < 22; j++)
        op_[j] = fmaxf(fmaf(acc[j], scv, shv), 0.0f);
}

// ---------------- conv1x1 (128 -> 170) ----------------
// grid (44 pos-tiles, 6 images), block 128: 64 positions x 2 oc-halves
__global__ void k_conv1x1(const float* __restrict__ w3, const float* __restrict__ b3) {
    __shared__ float xs[FC][64];
    int p0 = blockIdx.x * 64;
    int n  = blockIdx.y;
    int tid = threadIdx.x;
    for (int idx = tid; idx < FC*64; idx += 128) {
        int ic = idx >> 6, pos = idx & 63;
        xs[ic][pos] = g_x2[(n*FC + ic)*NPIX + p0 + pos];
    }
    __syncthreads();
    int half = tid >> 6, pos = tid & 63;
    int ocS = half * 85, ocE = ocS + 85;
    for (int oc = ocS; oc < ocE; oc++) {
        float acc = __ldg(&b3[oc]);
        #pragma unroll 8
        for (int ic = 0; ic < FC; ic++)
            acc = fmaf(xs[ic][pos], __ldg(&w3[oc*FC + ic]), acc);
        g_logits[(n*OC3 + oc)*NPIX + p0 + pos] = acc;
    }
}

// ---------------- gaussian prep (per-pixel) ----------------
__global__ void k_gauss() {
    int g = blockIdx.x * 128 + threadIdx.x;   // < 16896 (exact)
    int n = g / NPIX;
    int p = g - n*NPIX;
    int h = p / FW;
    int w = p - h*FW;
    const float* L = g_logits + n*OC3*NPIX + p;

    // softmax over 41 depth logits
    float lg[DLEV];
    float mval = -1e30f;
    #pragma unroll
    for (int d = 0; d < DLEV; d++) { lg[d] = L[d*NPIX]; mval = fmaxf(mval, lg[d]); }
    float sum = 0.0f;
    #pragma unroll
    for (int d = 0; d < DLEV; d++) { lg[d] = __expf(lg[d] - mval); sum += lg[d]; }
    float inv = 1.0f / sum;

    // camera geometry: p1 = base + depth*dir ; p2 = (p1x*p1z, p1y*p1z, p1z); p3 = comb@p2 + trans
    const float* cm = g_cam + n*24;
    float c00=cm[0], c01=cm[1], c02=cm[2], c10=cm[3], c11=cm[4], c12=cm[5];
    float i00=cm[9], i01=cm[10], i02=cm[11], i10=cm[12], i11=cm[13], i12=cm[14];
    float i20=cm[15], i21=cm[16], i22=cm[17];
    float tx=cm[18], ty=cm[19];
    float ptx=cm[21], pty=cm[22], ptz=cm[23];
    float xs = (float)w * (703.0f/87.0f);
    float ys = (float)h * (255.0f/31.0f);
    float b0 = xs - ptx, b1 = ys - pty, b2 = -ptz;
    float bx = i00*b0 + i01*b1 + i02*b2;
    float by = i10*b0 + i11*b1 + i12*b2;
    float bz = i20*b0 + i21*b1 + i22*b2;
    float dx = i02, dy = i12, dz = i22;

    float mex = 0.0f, mey = 0.0f;
    #pragma unroll
    for (int d = 0; d < DLEV; d++) {
        float dep = 4.0f + (float)d;
        float p1x = bx + dep*dx, p1y = by + dep*dy, p1z = bz + dep*dz;
        float p2x = p1x*p1z, p2y = p1y*p1z;
        float gx = c00*p2x + c01*p2y + c02*p1z + tx;
        float gy = c10*p2x + c11*p2y + c12*p1z + ty;
        float pr = lg[d]*inv;
        mex += pr*gx; mey += pr*gy;
    }
    float cxx = 0.0f, cxy = 0.0f, cyy = 0.0f;
    #pragma unroll
    for (int d = 0; d < DLEV; d++) {
        float dep = 4.0f + (float)d;
        float p1x = bx + dep*dx, p1y = by + dep*dy, p1z = bz + dep*dz;
        float p2x = p1x*p1z, p2y = p1y*p1z;
        float gx = c00*p2x + c01*p2y + c02*p1z + tx;
        float gy = c10*p2x + c11*p2y + c12*p1z + ty;
        float ddx = mex - gx, ddy = mey - gy;
        float pr = lg[d]*inv;
        cxx += pr*ddx*ddx; cxy += pr*ddx*ddy; cyy += pr*ddy*ddy;
    }
    // net scaling: sh^2 * (2/100)^2 * (tol^2/9) collapses to 1/9
    float a_ = cyy*(1.0f/9.0f) + 0.3f;   // multiplies dI^2 (rows ~ y)
    float c_ = cxx*(1.0f/9.0f) + 0.3f;   // multiplies dJ^2 (cols ~ x)
    float b_ = cxy*(1.0f/9.0f);
    float det = a_*c_ - b_*b_;

    float opl = L[DLEV*NPIX];
    float op = 1.0f / (1.0f + __expf(-opl));
    bool msk = (op > 0.05f);
    if (msk) atomicAdd(&g_cnt, 1);
    bool valid = msk && (det > 0.0f);
    float idet = valid ? (1.0f/det) : 0.0f;

    g_gMy[g] = 50.0f - mey;    // -sh*0.02*mey + 50
    g_gMx[g] = 50.0f - mex;
    g_gA[g]  = c_*idet;        // conic for dI^2
    g_gB[g]  = -b_*idet;
    g_gC[g]  = a_*idet;
    g_gOp[g] = op;
    g_gQ[g]  = valid ? 2.0f*logf(255.0f*op) : -1e30f;

    // transpose features: colors[g][c]
    float* cp = g_colors + g*OUTC;
    const float* fp_ = L + (DLEV+1)*NPIX;
    for (int c = 0; c < OUTC; c++) cp[c] = fp_[c*NPIX];
}

// ---------------- splat: ordered alpha compositing ----------------
// block 256 = 8 warps; warp handles 4 pixels; lane l screens gaussian (chunk+sub+l);
// active set composited in ascending gaussian order via ballot + ffs + shfl.
__global__ void k_splat(float* __restrict__ out) {
    int warp = threadIdx.x >> 5;
    int lane = threadIdx.x & 31;
    int pixBase = (blockIdx.x * 8 + warp) * 4;

    float pi[4], pj[4];
    #pragma unroll
    for (int k = 0; k < 4; k++) {
        int p = pixBase + k;
        if (p < P_TOT) {
            int row = p / BEV_W;
            pi[k] = (float)row;
            pj[k] = (float)(p - row*BEV_W);
        } else {
            pi[k] = 1e15f; pj[k] = 1e15f;
        }
    }
    float T[4] = {1.0f, 1.0f, 1.0f, 1.0f};
    float acc[16];
    #pragma unroll
    for (int j = 0; j < 16; j++) acc[j] = 0.0f;

    __shared__ float sMy[128], sMx[128], sA[128], sB[128], sC[128], sOp[128], sQ[128];

    for (int base = 0; base < G_TOT; base += 128) {
        __syncthreads();
        if (threadIdx.x < 128) {
            int gi = base + threadIdx.x;
            sMy[threadIdx.x] = g_gMy[gi];
            sMx[threadIdx.x] = g_gMx[gi];
            sA[threadIdx.x]  = g_gA[gi];
            sB[threadIdx.x]  = g_gB[gi];
            sC[threadIdx.x]  = g_gC[gi];
            sOp[threadIdx.x] = g_gOp[gi];
            sQ[threadIdx.x]  = g_gQ[gi];
        }
        __syncthreads();
        // all lanes hold identical T -> warp-uniform skip of saturated warps
        if (T[0] + T[1] + T[2] + T[3] < 1e-9f) continue;

        for (int sub = 0; sub < 128; sub += 32) {
            int gl = sub + lane;
            float my = sMy[gl], mxx = sMx[gl];
            float A = sA[gl], Bc = sB[gl], Cc = sC[gl];
            float op = sOp[gl], qm = sQ[gl];

            float al[4]; unsigned msk[4];
            #pragma unroll
            for (int k = 0; k < 4; k++) {
                float dI = pi[k] - my;
                float dJ = pj[k] - mxx;
                float q = dI*(A*dI + Bc*dJ) + dJ*(Bc*dI + Cc*dJ);
                float a_v = 0.0f;
                if (q >= 0.0f && q <= qm + 1e-3f) {
                    a_v = fminf(0.99f, op*__expf(-0.5f*q));
                    if (a_v < (1.0f/255.0f)) a_v = 0.0f;
                }
                al[k] = a_v;
                msk[k] = __ballot_sync(0xffffffffu, a_v > 0.0f);
            }
            unsigned un = msk[0] | msk[1] | msk[2] | msk[3];
            while (un) {
                int l = __ffs(un) - 1;
                un &= un - 1;
                const float4 col = *(const float4*)(g_colors + (base + sub + l)*OUTC + lane*4);
                #pragma unroll
                for (int k = 0; k < 4; k++) {
                    if ((msk[k] >> l) & 1u) {
                        float a = __shfl_sync(0xffffffffu, al[k], l);
                        float wv = a * T[k];
                        acc[k*4+0] = fmaf(wv, col.x, acc[k*4+0]);
                        acc[k*4+1] = fmaf(wv, col.y, acc[k*4+1]);
                        acc[k*4+2] = fmaf(wv, col.z, acc[k*4+2]);
                        acc[k*4+3] = fmaf(wv, col.w, acc[k*4+3]);
                        T[k] *= (1.0f - a);
                    }
                }
            }
        }
    }

    #pragma unroll
    for (int k = 0; k < 4; k++) {
        int p = pixBase + k;
        if (p < P_TOT) {
            #pragma unroll
            for (int j = 0; j < 4; j++)
                out[(lane*4 + j)*P_TOT + p] = acc[k*4 + j];
        }
    }
}

__global__ void k_count(float* __restrict__ dst) {
    dst[0] = (float)g_cnt;
}

// ---------------- launch ----------------
extern "C" void kernel_launch(void* const* d_in, const int* in_sizes, int n_in,
                              void* d_out, int out_size) {
    const float* rots   = (const float*)d_in[0];
    const float* trans  = (const float*)d_in[1];
    const float* intr   = (const float*)d_in[2];
    const float* prots  = (const float*)d_in[3];
    const float* ptrans = (const float*)d_in[4];
    const float* feats  = (const float*)d_in[5];
    const float* c1w = (const float*)d_in[6];
    const float* c1b = (const float*)d_in[7];
    const float* g1  = (const float*)d_in[8];
    const float* b1  = (const float*)d_in[9];
    const float* m1  = (const float*)d_in[10];
    const float* v1  = (const float*)d_in[11];
    const float* c2w = (const float*)d_in[12];
    const float* c2b = (const float*)d_in[13];
    const float* g2  = (const float*)d_in[14];
    const float* b2  = (const float*)d_in[15];
    const float* m2  = (const float*)d_in[16];
    const float* v2  = (const float*)d_in[17];
    const float* c3w = (const float*)d_in[18];
    const float* c3b = (const float*)d_in[19];
    float* out = (float*)d_out;

    k_setup<<<1, 256>>>(rots, trans, intr, prots, ptrans,
                        c1b, g1, b1, m1, v1, c2b, g2, b2, m2, v2);
    k_conv3x3<<<dim3(8, 8, 6), 256>>>(feats, c1w, 0);
    k_conv3x3<<<dim3(8, 8, 6), 256>>>(feats, c2w, 1);
    k_conv1x1<<<dim3(44, 6), 128>>>(c3w, c3b);
    k_gauss<<<132, 128>>>();
    k_splat<<<(P_TOT + 31)/32, 256>>>(out);
    if (out_size > P_TOT*OUTC)
        k_count<<<1, 1>>>(out + P_TOT*OUTC);
}

// round 6
// speedup vs baseline: 1.3232x; 1.3232x over previous
#include <cuda_runtime.h>

// ---------------- static config ----------------
#define NCAM   6
#define FC     128
#define FH     32
#define FW     88
#define NPIX   (FH*FW)          // 2816
#define DLEV   41
#define OC3    170              // 41 depth + 1 opacity + 128 feat
#define OUTC   128
#define G_TOT  (NCAM*NPIX)      // 16896
#define BEV_H  100
#define BEV_W  100
#define P_TOT  (BEV_H*BEV_W)    // 10000

// ---------------- scratch (device globals; no allocation) ----------------
__device__ float g_x1[NCAM*FC*NPIX];        // conv1 out
__device__ float g_x2[NCAM*FC*NPIX];        // conv2 out
__device__ float g_logits[NCAM*OC3*NPIX];   // conv3 out
__device__ float g_colors[G_TOT*OUTC];      // [g][c] transposed features
__device__ float g_gMy[G_TOT], g_gMx[G_TOT];
__device__ float g_gA[G_TOT], g_gB[G_TOT], g_gC[G_TOT];
__device__ float g_gOp[G_TOT], g_gQ[G_TOT];
__device__ float g_cam[NCAM*24];            // comb[9], invPostRot[9], trans[3], posttrans[3]
__device__ float g_sc1[FC], g_sh1[FC], g_sc2[FC], g_sh2[FC];
__device__ int   g_cnt;

// ---------------- setup ----------------
__device__ __forceinline__ void inv3(const float* m, float* o) {
    float a=m[0],b=m[1],c=m[2],d=m[3],e=m[4],f=m[5],g=m[6],h=m[7],i=m[8];
    float A =  (e*i - f*h);
    float B = -(d*i - f*g);
    float C =  (d*h - e*g);
    float det = a*A + b*B + c*C;
    float id = 1.0f/det;
    o[0]=A*id;            o[1]=-(b*i-c*h)*id;  o[2]= (b*f-c*e)*id;
    o[3]=B*id;            o[4]= (a*i-c*g)*id;  o[5]=-(a*f-c*d)*id;
    o[6]=C*id;            o[7]=-(a*h-b*g)*id;  o[8]= (a*e-b*d)*id;
}

__global__ void k_setup(const float* __restrict__ rots, const float* __restrict__ trans,
                        const float* __restrict__ intr, const float* __restrict__ prots,
                        const float* __restrict__ ptrans,
                        const float* __restrict__ c1b, const float* __restrict__ g1,
                        const float* __restrict__ b1,  const float* __restrict__ m1,
                        const float* __restrict__ v1,
                        const float* __restrict__ c2b, const float* __restrict__ g2,
                        const float* __restrict__ b2,  const float* __restrict__ m2,
                        const float* __restrict__ v2) {
    int t = threadIdx.x;
    if (t < NCAM) {
        float iK[9], iPR[9], comb[9];
        inv3(intr + t*9, iK);
        inv3(prots + t*9, iPR);
        const float* R = rots + t*9;
        #pragma unroll
        for (int r = 0; r < 3; r++)
            #pragma unroll
            for (int c = 0; c < 3; c++)
                comb[r*3+c] = R[r*3+0]*iK[0*3+c] + R[r*3+1]*iK[1*3+c] + R[r*3+2]*iK[2*3+c];
        float* o = g_cam + t*24;
        #pragma unroll
        for (int j = 0; j < 9; j++) o[j]   = comb[j];
        #pragma unroll
        for (int j = 0; j < 9; j++) o[9+j] = iPR[j];
        o[18]=trans[t*3+0]; o[19]=trans[t*3+1]; o[20]=trans[t*3+2];
        o[21]=ptrans[t*3+0]; o[22]=ptrans[t*3+1]; o[23]=ptrans[t*3+2];
    }
    if (t < FC) {
        float s1 = g1[t]*rsqrtf(v1[t] + 1e-3f);
        g_sc1[t] = s1;
        g_sh1[t] = (c1b[t] - m1[t])*s1 + b1[t];
        float s2 = g2[t]*rsqrtf(v2[t] + 1e-3f);
        g_sc2[t] = s2;
        g_sh2[t] = (c2b[t] - m2[t])*s2 + b2[t];
    }
    if (t == 0) g_cnt = 0;
}

// ---------------- conv3x3 + BN + ReLU ----------------
__global__ void k_conv3x3(const float* __restrict__ feats,
                          const float* __restrict__ wgt,
                          int which) {
    __shared__ float sIn[6][90];
    __shared__ float sW[16][9];
    const float* inp = which ? g_x1 : feats;
    float*       out = which ? g_x2 : g_x1;
    const float* sc  = which ? g_sc2 : g_sc1;
    const float* sh  = which ? g_sh2 : g_sh1;

    int h0  = blockIdx.x * 4;
    int oc0 = blockIdx.y * 16;
    int n   = blockIdx.z;
    int tid = threadIdx.x;
    int oc_l = tid >> 4;
    int s    = tid & 15;
    int r    = s >> 2;
    int c0   = (s & 3) * 22;

    float acc[22];
    #pragma unroll
    for (int j = 0; j < 22; j++) acc[j] = 0.0f;

    for (int ic = 0; ic < FC; ic++) {
        __syncthreads();
        for (int idx = tid; idx < 540; idx += 256) {
            int rr = idx / 90, cc = idx - rr*90;
            int gh = h0 - 1 + rr, gw = cc - 1;
            float v = 0.0f;
            if ((unsigned)gh < FH && (unsigned)gw < FW)
                v = inp[((n*FC + ic)*FH + gh)*FW + gw];
            sIn[rr][cc] = v;
        }
        if (tid < 144) {
            int ocl = tid / 9, kk = tid - ocl*9;
            sW[ocl][kk] = wgt[((oc0 + ocl)*FC + ic)*9 + kk];
        }
        __syncthreads();

        float wv[9];
        #pragma unroll
        for (int t2 = 0; t2 < 9; t2++) wv[t2] = sW[oc_l][t2];
        #pragma unroll
        for (int kh = 0; kh < 3; kh++) {
            const float* rp = &sIn[r + kh][c0];
            float ld[24];
            #pragma unroll
            for (int j = 0; j < 24; j++) ld[j] = rp[j];
            #pragma unroll
            for (int j = 0; j < 22; j++)
                acc[j] = fmaf(wv[kh*3+0], ld[j],
                          fmaf(wv[kh*3+1], ld[j+1],
                           fmaf(wv[kh*3+2], ld[j+2], acc[j])));
        }
    }

    int oc = oc0 + oc_l;
    float scv = sc[oc], shv = sh[oc];
    float* op_ = out + ((n*FC + oc)*FH + (h0 + r))*FW + c0;
    #pragma unroll
    for (int j = 0; j < 22; j++)
        op_[j] = fmaxf(fmaf(acc[j], scv, shv), 0.0f);
}

// ---------------- conv1x1 as tiled GEMM (170 x 2816 per image, K=128) ----------------
// grid (44 pos-tiles, 3 oc-tiles, 6 images), block 256 = 16x16, 4x4 micro-tile.
__global__ void k_conv1x1(const float* __restrict__ w3, const float* __restrict__ b3) {
    __shared__ float sW[16][64];   // [k][oc]
    __shared__ float sX[16][64];   // [k][pos]
    int p0  = blockIdx.x * 64;
    int oc0 = blockIdx.y * 64;
    int n   = blockIdx.z;
    int tid = threadIdx.x;
    int tx  = tid & 15;    // pos quad
    int ty  = tid >> 4;    // oc quad

    float acc[4][4];
    #pragma unroll
    for (int i = 0; i < 4; i++)
        #pragma unroll
        for (int j = 0; j < 4; j++) acc[i][j] = 0.0f;

    for (int k0 = 0; k0 < FC; k0 += 16) {
        #pragma unroll
        for (int i = tid; i < 16*64; i += 256) {
            int kk = i >> 6, oc = i & 63;
            int ocg = oc0 + oc;
            sW[kk][oc] = (ocg < OC3) ? w3[ocg*FC + k0 + kk] : 0.0f;
        }
        #pragma unroll
        for (int i = tid; i < 16*64; i += 256) {
            int kk = i >> 6, pp = i & 63;
            sX[kk][pp] = g_x2[(n*FC + k0 + kk)*NPIX + p0 + pp];
        }
        __syncthreads();
        #pragma unroll
        for (int kk = 0; kk < 16; kk++) {
            float xv[4], wv[4];
            #pragma unroll
            for (int j = 0; j < 4; j++) xv[j] = sX[kk][tx*4 + j];
            #pragma unroll
            for (int i = 0; i < 4; i++) wv[i] = sW[kk][ty*4 + i];
            #pragma unroll
            for (int i = 0; i < 4; i++)
                #pragma unroll
                for (int j = 0; j < 4; j++)
                    acc[i][j] = fmaf(wv[i], xv[j], acc[i][j]);
        }
        __syncthreads();
    }
    #pragma unroll
    for (int i = 0; i < 4; i++) {
        int oc = oc0 + ty*4 + i;
        if (oc < OC3) {
            float bb = __ldg(&b3[oc]);
            #pragma unroll
            for (int j = 0; j < 4; j++)
                g_logits[(n*OC3 + oc)*NPIX + p0 + tx*4 + j] = acc[i][j] + bb;
        }
    }
}

// ---------------- gaussian prep (per-pixel) ----------------
__global__ void k_gauss() {
    int g = blockIdx.x * 128 + threadIdx.x;   // < 16896 (exact)
    int n = g / NPIX;
    int p = g - n*NPIX;
    int h = p / FW;
    int w = p - h*FW;
    const float* L = g_logits + n*OC3*NPIX + p;

    // softmax over 41 depth logits
    float lg[DLEV];
    float mval = -1e30f;
    #pragma unroll
    for (int d = 0; d < DLEV; d++) { lg[d] = L[d*NPIX]; mval = fmaxf(mval, lg[d]); }
    float sum = 0.0f;
    #pragma unroll
    for (int d = 0; d < DLEV; d++) { lg[d] = __expf(lg[d] - mval); sum += lg[d]; }
    float inv = 1.0f / sum;

    const float* cm = g_cam + n*24;
    float c00=cm[0], c01=cm[1], c02=cm[2], c10=cm[3], c11=cm[4], c12=cm[5];
    float i00=cm[9], i01=cm[10], i02=cm[11], i10=cm[12], i11=cm[13], i12=cm[14];
    float i20=cm[15], i21=cm[16], i22=cm[17];
    float tx=cm[18], ty=cm[19];
    float ptx=cm[21], pty=cm[22], ptz=cm[23];
    float xs = (float)w * (703.0f/87.0f);
    float ys = (float)h * (255.0f/31.0f);
    float b0 = xs - ptx, b1 = ys - pty, b2 = -ptz;
    float bx = i00*b0 + i01*b1 + i02*b2;
    float by = i10*b0 + i11*b1 + i12*b2;
    float bz = i20*b0 + i21*b1 + i22*b2;
    float dx = i02, dy = i12, dz = i22;

    float mex = 0.0f, mey = 0.0f;
    #pragma unroll
    for (int d = 0; d < DLEV; d++) {
        float dep = 4.0f + (float)d;
        float p1x = bx + dep*dx, p1y = by + dep*dy, p1z = bz + dep*dz;
        float p2x = p1x*p1z, p2y = p1y*p1z;
        float gx = c00*p2x + c01*p2y + c02*p1z + tx;
        float gy = c10*p2x + c11*p2y + c12*p1z + ty;
        float pr = lg[d]*inv;
        mex += pr*gx; mey += pr*gy;
    }
    float cxx = 0.0f, cxy = 0.0f, cyy = 0.0f;
    #pragma unroll
    for (int d = 0; d < DLEV; d++) {
        float dep = 4.0f + (float)d;
        float p1x = bx + dep*dx, p1y = by + dep*dy, p1z = bz + dep*dz;
        float p2x = p1x*p1z, p2y = p1y*p1z;
        float gx = c00*p2x + c01*p2y + c02*p1z + tx;
        float gy = c10*p2x + c11*p2y + c12*p1z + ty;
        float ddx = mex - gx, ddy = mey - gy;
        float pr = lg[d]*inv;
        cxx += pr*ddx*ddx; cxy += pr*ddx*ddy; cyy += pr*ddy*ddy;
    }
    float a_ = cyy*(1.0f/9.0f) + 0.3f;
    float c_ = cxx*(1.0f/9.0f) + 0.3f;
    float b_ = cxy*(1.0f/9.0f);
    float det = a_*c_ - b_*b_;

    float opl = L[DLEV*NPIX];
    float op = 1.0f / (1.0f + __expf(-opl));
    bool msk = (op > 0.05f);
    if (msk) atomicAdd(&g_cnt, 1);
    bool valid = msk && (det > 0.0f);
    float idet = valid ? (1.0f/det) : 0.0f;

    g_gMy[g] = 50.0f - mey;
    g_gMx[g] = 50.0f - mex;
    g_gA[g]  = c_*idet;
    g_gB[g]  = -b_*idet;
    g_gC[g]  = a_*idet;
    g_gOp[g] = op;
    g_gQ[g]  = valid ? 2.0f*logf(255.0f*op) : -1e30f;

    // transpose features: colors[g][c] with vectorized stores
    float4* cp4 = (float4*)(g_colors + g*OUTC);
    const float* fp_ = L + (DLEV+1)*NPIX;
    #pragma unroll
    for (int c = 0; c < OUTC; c += 4) {
        float4 v;
        v.x = fp_[(c+0)*NPIX];
        v.y = fp_[(c+1)*NPIX];
        v.z = fp_[(c+2)*NPIX];
        v.w = fp_[(c+3)*NPIX];
        cp4[c >> 2] = v;
    }
}

// ---------------- splat: ordered alpha compositing, 8 px per warp ----------------
__global__ void k_splat(float* __restrict__ out) {
    int warp = threadIdx.x >> 5;
    int lane = threadIdx.x & 31;
    int pixBase = (blockIdx.x * 8 + warp) * 8;

    float pi[8], pj[8];
    #pragma unroll
    for (int k = 0; k < 8; k++) {
        int p = pixBase + k;
        if (p < P_TOT) {
            int row = p / BEV_W;
            pi[k] = (float)row;
            pj[k] = (float)(p - row*BEV_W);
        } else {
            pi[k] = 1e15f; pj[k] = 1e15f;
        }
    }
    float T[8];
    #pragma unroll
    for (int k = 0; k < 8; k++) T[k] = 1.0f;
    float acc[32];
    #pragma unroll
    for (int j = 0; j < 32; j++) acc[j] = 0.0f;

    __shared__ float sMy[128], sMx[128], sA[128], sB[128], sC[128], sOp[128], sQ[128];

    for (int base = 0; base < G_TOT; base += 128) {
        __syncthreads();
        if (threadIdx.x < 128) {
            int gi = base + threadIdx.x;
            sMy[threadIdx.x] = g_gMy[gi];
            sMx[threadIdx.x] = g_gMx[gi];
            sA[threadIdx.x]  = g_gA[gi];
            sB[threadIdx.x]  = g_gB[gi];
            sC[threadIdx.x]  = g_gC[gi];
            sOp[threadIdx.x] = g_gOp[gi];
            sQ[threadIdx.x]  = g_gQ[gi];
        }
        __syncthreads();
        float ts = 0.0f;
        #pragma unroll
        for (int k = 0; k < 8; k++) ts += T[k];
        if (ts < 1e-9f) continue;   // warp-uniform (all lanes hold identical T)

        for (int sub = 0; sub < 128; sub += 32) {
            int gl = sub + lane;
            float my = sMy[gl], mxx = sMx[gl];
            float A = sA[gl], Bc = sB[gl], Cc = sC[gl];
            float op = sOp[gl], qm = sQ[gl];

            float al[8]; unsigned msk[8];
            #pragma unroll
            for (int k = 0; k < 8; k++) {
                float dI = pi[k] - my;
                float dJ = pj[k] - mxx;
                float q = dI*(A*dI + Bc*dJ) + dJ*(Bc*dI + Cc*dJ);
                float a_v = 0.0f;
                if (q >= 0.0f && q <= qm + 1e-3f) {
                    a_v = fminf(0.99f, op*__expf(-0.5f*q));
                    if (a_v < (1.0f/255.0f)) a_v = 0.0f;
                }
                al[k] = a_v;
                msk[k] = __ballot_sync(0xffffffffu, a_v > 0.0f);
            }
            unsigned un = msk[0] | msk[1] | msk[2] | msk[3]
                        | msk[4] | msk[5] | msk[6] | msk[7];
            while (un) {
                int l = __ffs(un) - 1;
                un &= un - 1;
                const float4 col = *(const float4*)(g_colors + (base + sub + l)*OUTC + lane*4);
                #pragma unroll
                for (int k = 0; k < 8; k++) {
                    if ((msk[k] >> l) & 1u) {
                        float a = __shfl_sync(0xffffffffu, al[k], l);
                        float wv = a * T[k];
                        acc[k*4+0] = fmaf(wv, col.x, acc[k*4+0]);
                        acc[k*4+1] = fmaf(wv, col.y, acc[k*4+1]);
                        acc[k*4+2] = fmaf(wv, col.z, acc[k*4+2]);
                        acc[k*4+3] = fmaf(wv, col.w, acc[k*4+3]);
                        T[k] *= (1.0f - a);
                    }
                }
            }
        }
    }

    #pragma unroll
    for (int k = 0; k < 8; k++) {
        int p = pixBase + k;
        if (p < P_TOT) {
            #pragma unroll
            for (int j = 0; j < 4; j++)
                out[(lane*4 + j)*P_TOT + p] = acc[k*4 + j];
        }
    }
}

__global__ void k_count(float* __restrict__ dst) {
    dst[0] = (float)g_cnt;
}

// ---------------- launch ----------------
extern "C" void kernel_launch(void* const* d_in, const int* in_sizes, int n_in,
                              void* d_out, int out_size) {
    const float* rots   = (const float*)d_in[0];
    const float* trans  = (const float*)d_in[1];
    const float* intr   = (const float*)d_in[2];
    const float* prots  = (const float*)d_in[3];
    const float* ptrans = (const float*)d_in[4];
    const float* feats  = (const float*)d_in[5];
    const float* c1w = (const float*)d_in[6];
    const float* c1b = (const float*)d_in[7];
    const float* g1  = (const float*)d_in[8];
    const float* b1  = (const float*)d_in[9];
    const float* m1  = (const float*)d_in[10];
    const float* v1  = (const float*)d_in[11];
    const float* c2w = (const float*)d_in[12];
    const float* c2b = (const float*)d_in[13];
    const float* g2  = (const float*)d_in[14];
    const float* b2  = (const float*)d_in[15];
    const float* m2  = (const float*)d_in[16];
    const float* v2  = (const float*)d_in[17];
    const float* c3w = (const float*)d_in[18];
    const float* c3b = (const float*)d_in[19];
    float* out = (float*)d_out;

    k_setup<<<1, 256>>>(rots, trans, intr, prots, ptrans,
                        c1b, g1, b1, m1, v1, c2b, g2, b2, m2, v2);
    k_conv3x3<<<dim3(8, 8, 6), 256>>>(feats, c1w, 0);
    k_conv3x3<<<dim3(8, 8, 6), 256>>>(feats, c2w, 1);
    k_conv1x1<<<dim3(44, 3, 6), 256>>>(c3w, c3b);
    k_gauss<<<132, 128>>>();
    k_splat<<<(P_TOT + 63)/64, 256>>>(out);
    if (out_size > P_TOT*OUTC)
        k_count<<<1, 1>>>(out + P_TOT*OUTC);
}

// round 7
// speedup vs baseline: 1.4076x; 1.0637x over previous
#include <cuda_runtime.h>

// ---------------- static config ----------------
#define NCAM   6
#define FC     128
#define FH     32
#define FW     88
#define NPIX   (FH*FW)          // 2816
#define DLEV   41
#define OC3    170              // 41 depth + 1 opacity + 128 feat
#define OUTC   128
#define G_TOT  (NCAM*NPIX)      // 16896
#define BEV_H  100
#define BEV_W  100
#define P_TOT  (BEV_H*BEV_W)    // 10000
#define KTOT   (9*FC)           // 1152

// ---------------- scratch (device globals; no allocation) ----------------
__device__ float g_x1[NCAM*FC*NPIX];        // conv1 out
__device__ float g_x2[NCAM*FC*NPIX];        // conv2 out
__device__ float g_logits[NCAM*OC3*NPIX];   // conv3 out
__device__ float g_colors[G_TOT*OUTC];      // [g][c] transposed features
__device__ float g_wt1[KTOT*FC];            // conv1 weights [k=s*128+ic][oc]
__device__ float g_wt2[KTOT*FC];
__device__ float4 g_pk0[G_TOT], g_pk1[G_TOT];
__device__ int   g_rmin[G_TOT], g_rmax[G_TOT];
__device__ int   g_list[BEV_H*G_TOT];       // per-row gaussian lists (ascending g)
__device__ int   g_len[BEV_H];
__device__ float g_cam[NCAM*24];
__device__ float g_sc1[FC], g_sh1[FC], g_sc2[FC], g_sh2[FC];
__device__ int   g_cnt;

// ---------------- setup ----------------
__device__ __forceinline__ void inv3(const float* m, float* o) {
    float a=m[0],b=m[1],c=m[2],d=m[3],e=m[4],f=m[5],g=m[6],h=m[7],i=m[8];
    float A =  (e*i - f*h);
    float B = -(d*i - f*g);
    float C =  (d*h - e*g);
    float det = a*A + b*B + c*C;
    float id = 1.0f/det;
    o[0]=A*id;            o[1]=-(b*i-c*h)*id;  o[2]= (b*f-c*e)*id;
    o[3]=B*id;            o[4]= (a*i-c*g)*id;  o[5]=-(a*f-c*d)*id;
    o[6]=C*id;            o[7]=-(a*h-b*g)*id;  o[8]= (a*e-b*d)*id;
}

__global__ void k_setup(const float* __restrict__ rots, const float* __restrict__ trans,
                        const float* __restrict__ intr, const float* __restrict__ prots,
                        const float* __restrict__ ptrans,
                        const float* __restrict__ c1b, const float* __restrict__ g1,
                        const float* __restrict__ b1,  const float* __restrict__ m1,
                        const float* __restrict__ v1,
                        const float* __restrict__ c2b, const float* __restrict__ g2,
                        const float* __restrict__ b2,  const float* __restrict__ m2,
                        const float* __restrict__ v2) {
    int t = threadIdx.x;
    if (t < NCAM) {
        float iK[9], iPR[9], comb[9];
        inv3(intr + t*9, iK);
        inv3(prots + t*9, iPR);
        const float* R = rots + t*9;
        #pragma unroll
        for (int r = 0; r < 3; r++)
            #pragma unroll
            for (int c = 0; c < 3; c++)
                comb[r*3+c] = R[r*3+0]*iK[0*3+c] + R[r*3+1]*iK[1*3+c] + R[r*3+2]*iK[2*3+c];
        float* o = g_cam + t*24;
        #pragma unroll
        for (int j = 0; j < 9; j++) o[j]   = comb[j];
        #pragma unroll
        for (int j = 0; j < 9; j++) o[9+j] = iPR[j];
        o[18]=trans[t*3+0]; o[19]=trans[t*3+1]; o[20]=trans[t*3+2];
        o[21]=ptrans[t*3+0]; o[22]=ptrans[t*3+1]; o[23]=ptrans[t*3+2];
    }
    if (t < FC) {
        float s1 = g1[t]*rsqrtf(v1[t] + 1e-3f);
        g_sc1[t] = s1;
        g_sh1[t] = (c1b[t] - m1[t])*s1 + b1[t];
        float s2 = g2[t]*rsqrtf(v2[t] + 1e-3f);
        g_sc2[t] = s2;
        g_sh2[t] = (c2b[t] - m2[t])*s2 + b2[t];
    }
    if (t == 0) g_cnt = 0;
}

// ---------------- weight transpose: [oc][ic][3][3] -> [s*128+ic][oc] ----------------
__global__ void k_wtrans(const float* __restrict__ w1, const float* __restrict__ w2) {
    int i = blockIdx.x * 256 + threadIdx.x;     // 576 blocks, exact 147456
    int k  = i >> 7, oc = i & 127;
    int s  = k >> 7, ic = k & 127;
    int src = oc*KTOT + ic*9 + s;               // oc*1152 + ic*9 + s
    g_wt1[i] = w1[src];
    g_wt2[i] = w2[src];
}

// ---------------- conv3x3 as implicit GEMM (128 oc x 64 px tiles, K=1152) --------
// grid (44 px-tiles, 6 images), block 256 = 16x16, micro-tile 8 oc x 4 px.
__global__ void k_conv3g(const float* __restrict__ feats, int layer) {
    __shared__ float sW[16][128];
    __shared__ float sX[16][64];
    const float* in_ = layer ? g_x1 : feats;
    const float* wt  = layer ? g_wt2 : g_wt1;
    float*       out = layer ? g_x2  : g_x1;
    const float* sc  = layer ? g_sc2 : g_sc1;
    const float* sh  = layer ? g_sh2 : g_sh1;

    int p0 = blockIdx.x * 64;
    int n  = blockIdx.y;
    int tid = threadIdx.x;
    int tx = tid & 15;     // px quad
    int ty = tid >> 4;     // oc oct

    float acc[8][4];
    #pragma unroll
    for (int i = 0; i < 8; i++)
        #pragma unroll
        for (int j = 0; j < 4; j++) acc[i][j] = 0.0f;

    const float* inBase = in_ + n*FC*NPIX;

    for (int s = 0; s < 9; s++) {
        int dh = s/3 - 1, dw = s%3 - 1;
        int doff = dh*FW + dw;
        for (int ic0 = 0; ic0 < FC; ic0 += 16) {
            __syncthreads();
            // stage W: 16 k-rows x 128 oc (float4, coalesced)
            {
                int k0 = s*FC + ic0;
                #pragma unroll
                for (int u = 0; u < 2; u++) {
                    int e  = tid + u*256;       // float4 index, 512 total
                    int kk = e >> 5, cv = e & 31;
                    ((float4*)&sW[kk][0])[cv] = ((const float4*)&wt[(k0+kk)*FC])[cv];
                }
            }
            // stage X: 16 k-rows x 64 px with shift + zero-pad
            #pragma unroll
            for (int u = 0; u < 4; u++) {
                int e  = tid + u*256;           // scalar index, 1024 total
                int kk = e >> 6, pp = e & 63;
                int p = p0 + pp;
                int h = p / FW, w = p - h*FW;
                int hh = h + dh, ww = w + dw;
                float v = 0.0f;
                if ((unsigned)hh < FH && (unsigned)ww < FW)
                    v = inBase[(ic0+kk)*NPIX + p + doff];
                sX[kk][pp] = v;
            }
            __syncthreads();
            #pragma unroll
            for (int kk = 0; kk < 16; kk++) {
                float4 xv = *(const float4*)&sX[kk][tx*4];
                float4 w0 = *(const float4*)&sW[kk][ty*8];
                float4 w1 = *(const float4*)&sW[kk][ty*8+4];
                float wv[8] = {w0.x,w0.y,w0.z,w0.w,w1.x,w1.y,w1.z,w1.w};
                float xr[4] = {xv.x,xv.y,xv.z,xv.w};
                #pragma unroll
                for (int i = 0; i < 8; i++)
                    #pragma unroll
                    for (int j = 0; j < 4; j++)
                        acc[i][j] = fmaf(wv[i], xr[j], acc[i][j]);
            }
        }
    }

    #pragma unroll
    for (int i = 0; i < 8; i++) {
        int oc = ty*8 + i;
        float scv = sc[oc], shv = sh[oc];
        float* op_ = out + (n*FC + oc)*NPIX + p0 + tx*4;
        #pragma unroll
        for (int j = 0; j < 4; j++)
            op_[j] = fmaxf(fmaf(acc[i][j], scv, shv), 0.0f);
    }
}

// ---------------- conv1x1 as tiled GEMM (170 x 2816 per image, K=128) ------------
__global__ void k_conv1x1(const float* __restrict__ w3, const float* __restrict__ b3) {
    __shared__ float sW[16][64];
    __shared__ float sX[16][64];
    int p0  = blockIdx.x * 64;
    int oc0 = blockIdx.y * 64;
    int n   = blockIdx.z;
    int tid = threadIdx.x;
    int tx  = tid & 15;
    int ty  = tid >> 4;

    float acc[4][4];
    #pragma unroll
    for (int i = 0; i < 4; i++)
        #pragma unroll
        for (int j = 0; j < 4; j++) acc[i][j] = 0.0f;

    for (int k0 = 0; k0 < FC; k0 += 16) {
        #pragma unroll
        for (int i = tid; i < 16*64; i += 256) {
            int kk = i >> 6, oc = i & 63;
            int ocg = oc0 + oc;
            sW[kk][oc] = (ocg < OC3) ? w3[ocg*FC + k0 + kk] : 0.0f;
        }
        #pragma unroll
        for (int i = tid; i < 16*64; i += 256) {
            int kk = i >> 6, pp = i & 63;
            sX[kk][pp] = g_x2[(n*FC + k0 + kk)*NPIX + p0 + pp];
        }
        __syncthreads();
        #pragma unroll
        for (int kk = 0; kk < 16; kk++) {
            float xv[4], wv[4];
            #pragma unroll
            for (int j = 0; j < 4; j++) xv[j] = sX[kk][tx*4 + j];
            #pragma unroll
            for (int i = 0; i < 4; i++) wv[i] = sW[kk][ty*4 + i];
            #pragma unroll
            for (int i = 0; i < 4; i++)
                #pragma unroll
                for (int j = 0; j < 4; j++)
                    acc[i][j] = fmaf(wv[i], xv[j], acc[i][j]);
        }
        __syncthreads();
    }
    #pragma unroll
    for (int i = 0; i < 4; i++) {
        int oc = oc0 + ty*4 + i;
        if (oc < OC3) {
            float bb = __ldg(&b3[oc]);
            #pragma unroll
            for (int j = 0; j < 4; j++)
                g_logits[(n*OC3 + oc)*NPIX + p0 + tx*4 + j] = acc[i][j] + bb;
        }
    }
}

// ---------------- gaussian prep (per-pixel) ----------------
__global__ void k_gauss() {
    int g = blockIdx.x * 128 + threadIdx.x;   // < 16896 (exact)
    int n = g / NPIX;
    int p = g - n*NPIX;
    int h = p / FW;
    int w = p - h*FW;
    const float* L = g_logits + n*OC3*NPIX + p;

    float lg[DLEV];
    float mval = -1e30f;
    #pragma unroll
    for (int d = 0; d < DLEV; d++) { lg[d] = L[d*NPIX]; mval = fmaxf(mval, lg[d]); }
    float sum = 0.0f;
    #pragma unroll
    for (int d = 0; d < DLEV; d++) { lg[d] = __expf(lg[d] - mval); sum += lg[d]; }
    float inv = 1.0f / sum;

    const float* cm = g_cam + n*24;
    float c00=cm[0], c01=cm[1], c02=cm[2], c10=cm[3], c11=cm[4], c12=cm[5];
    float i00=cm[9], i01=cm[10], i02=cm[11], i10=cm[12], i11=cm[13], i12=cm[14];
    float i20=cm[15], i21=cm[16], i22=cm[17];
    float tx=cm[18], ty=cm[19];
    float ptx=cm[21], pty=cm[22], ptz=cm[23];
    float xs = (float)w * (703.0f/87.0f);
    float ys = (float)h * (255.0f/31.0f);
    float b0 = xs - ptx, b1 = ys - pty, b2 = -ptz;
    float bx = i00*b0 + i01*b1 + i02*b2;
    float by = i10*b0 + i11*b1 + i12*b2;
    float bz = i20*b0 + i21*b1 + i22*b2;
    float dx = i02, dy = i12, dz = i22;

    float mex = 0.0f, mey = 0.0f;
    #pragma unroll
    for (int d = 0; d < DLEV; d++) {
        float dep = 4.0f + (float)d;
        float p1x = bx + dep*dx, p1y = by + dep*dy, p1z = bz + dep*dz;
        float p2x = p1x*p1z, p2y = p1y*p1z;
        float gx = c00*p2x + c01*p2y + c02*p1z + tx;
        float gy = c10*p2x + c11*p2y + c12*p1z + ty;
        float pr = lg[d]*inv;
        mex += pr*gx; mey += pr*gy;
    }
    float cxx = 0.0f, cxy = 0.0f, cyy = 0.0f;
    #pragma unroll
    for (int d = 0; d < DLEV; d++) {
        float dep = 4.0f + (float)d;
        float p1x = bx + dep*dx, p1y = by + dep*dy, p1z = bz + dep*dz;
        float p2x = p1x*p1z, p2y = p1y*p1z;
        float gx = c00*p2x + c01*p2y + c02*p1z + tx;
        float gy = c10*p2x + c11*p2y + c12*p1z + ty;
        float ddx = mex - gx, ddy = mey - gy;
        float pr = lg[d]*inv;
        cxx += pr*ddx*ddx; cxy += pr*ddx*ddy; cyy += pr*ddy*ddy;
    }
    float a_ = cyy*(1.0f/9.0f) + 0.3f;   // row (i) variance
    float c_ = cxx*(1.0f/9.0f) + 0.3f;   // col (j) variance
    float b_ = cxy*(1.0f/9.0f);
    float det = a_*c_ - b_*b_;

    float opl = L[DLEV*NPIX];
    float op = 1.0f / (1.0f + __expf(-opl));
    bool msk = (op > 0.05f);
    if (msk) atomicAdd(&g_cnt, 1);
    bool valid = msk && (det > 0.0f);
    float idet = valid ? (1.0f/det) : 0.0f;

    float my = 50.0f - mey;
    float mx = 50.0f - mex;
    float qm = valid ? 2.0f*logf(255.0f*op) : -1e30f;

    g_pk0[g] = make_float4(my, mx, c_*idet, -b_*idet);
    g_pk1[g] = make_float4(a_*idet, op, qm, 0.0f);

    int r0 = 1, r1 = 0;
    if (valid) {
        float ext = sqrtf(fmaxf(qm, 0.0f)*a_) + 0.6f;
        r0 = max(0,  (int)ceilf(my - ext));
        r1 = min(99, (int)floorf(my + ext));
    }
    g_rmin[g] = r0;
    g_rmax[g] = r1;

    float4* cp4 = (float4*)(g_colors + g*OUTC);
    const float* fp_ = L + (DLEV+1)*NPIX;
    #pragma unroll
    for (int c = 0; c < OUTC; c += 4) {
        float4 v;
        v.x = fp_[(c+0)*NPIX];
        v.y = fp_[(c+1)*NPIX];
        v.z = fp_[(c+2)*NPIX];
        v.w = fp_[(c+3)*NPIX];
        cp4[c >> 2] = v;
    }
}

// ---------------- per-row ordered list build (stable compaction) ----------------
__global__ void k_rows() {
    int r = blockIdx.x;
    int tid = threadIdx.x, lane = tid & 31, wid = tid >> 5;
    __shared__ int sCnt[8];
    __shared__ int sOff, sTot;
    if (tid == 0) sOff = 0;
    __syncthreads();
    for (int base = 0; base < G_TOT; base += 256) {   // 66 exact chunks
        int g = base + tid;
        bool f = (g_rmin[g] <= r) && (r <= g_rmax[g]);
        unsigned b = __ballot_sync(0xffffffffu, f);
        if (lane == 0) sCnt[wid] = __popc(b);
        __syncthreads();
        if (tid == 0) {
            int t = 0;
            #pragma unroll
            for (int i = 0; i < 8; i++) { int c = sCnt[i]; sCnt[i] = t; t += c; }
            sTot = t;
        }
        __syncthreads();
        if (f) {
            int pos = sOff + sCnt[wid] + __popc(b & ((1u << lane) - 1u));
            g_list[r*G_TOT + pos] = g;
        }
        __syncthreads();
        if (tid == 0) sOff += sTot;
        __syncthreads();
    }
    if (tid == 0) g_len[r] = sOff;
}

// ---------------- splat: per-row lists, ordered alpha compositing ----------------
// block = one BEV row = 13 warps * 32; warp covers 8 consecutive cols.
__global__ void k_splat2(float* __restrict__ out) {
    int r = blockIdx.x;
    int warp = threadIdx.x >> 5;
    int lane = threadIdx.x & 31;
    int col0 = warp * 8;
    float fi = (float)r;

    float pj[8], T[8], acc[32];
    #pragma unroll
    for (int k = 0; k < 8; k++) {
        int c = col0 + k;
        pj[k] = (c < BEV_W) ? (float)c : 1e15f;
        T[k]  = (c < BEV_W) ? 1.0f : 0.0f;
    }
    #pragma unroll
    for (int j = 0; j < 32; j++) acc[j] = 0.0f;

    __shared__ int   sId[128];
    __shared__ float sP[128][9];    // pad 9: conflict-free strided reads

    int len = g_len[r];
    const int* lst = g_list + r*G_TOT;

    for (int c0 = 0; c0 < len; c0 += 128) {
        __syncthreads();
        if (threadIdx.x < 128) {
            int idx = c0 + threadIdx.x;
            if (idx < len) {
                int gid = lst[idx];
                sId[threadIdx.x] = gid;
                float4 a = g_pk0[gid];
                float4 b = g_pk1[gid];
                sP[threadIdx.x][0] = a.x; sP[threadIdx.x][1] = a.y;
                sP[threadIdx.x][2] = a.z; sP[threadIdx.x][3] = a.w;
                sP[threadIdx.x][4] = b.x; sP[threadIdx.x][5] = b.y;
                sP[threadIdx.x][6] = b.z;
            } else {
                sId[threadIdx.x] = 0;
                sP[threadIdx.x][0] = 0.0f; sP[threadIdx.x][1] = 0.0f;
                sP[threadIdx.x][2] = 0.0f; sP[threadIdx.x][3] = 0.0f;
                sP[threadIdx.x][4] = 0.0f; sP[threadIdx.x][5] = 0.0f;
                sP[threadIdx.x][6] = -1e30f;
            }
        }
        __syncthreads();

        float ts = 0.0f;
        #pragma unroll
        for (int k = 0; k < 8; k++) ts += T[k];
        if (ts < 1e-9f) continue;   // warp-uniform

        for (int sub = 0; sub < 128; sub += 32) {
            int gl = sub + lane;
            float my = sP[gl][0], mxx = sP[gl][1];
            float A  = sP[gl][2], Bc  = sP[gl][3], Cc = sP[gl][4];
            float op = sP[gl][5], qm  = sP[gl][6];

            float dI = fi - my;
            float c1 = A*dI*dI;
            float c2 = 2.0f*Bc*dI;

            float al[8]; unsigned msk[8];
            #pragma unroll
            for (int k = 0; k < 8; k++) {
                float dJ = pj[k] - mxx;
                float q = c1 + c2*dJ + Cc*dJ*dJ;
                float a_v = 0.0f;
                if (q >= 0.0f && q <= qm + 1e-3f) {
                    a_v = fminf(0.99f, op*__expf(-0.5f*q));
                    if (a_v < (1.0f/255.0f)) a_v = 0.0f;
                }
                al[k] = a_v;
                msk[k] = __ballot_sync(0xffffffffu, a_v > 0.0f);
            }
            unsigned un = msk[0] | msk[1] | msk[2] | msk[3]
                        | msk[4] | msk[5] | msk[6] | msk[7];
            while (un) {
                int l = __ffs(un) - 1;
                un &= un - 1;
                int gid = sId[sub + l];
                const float4 col = *(const float4*)(g_colors + gid*OUTC + lane*4);
                #pragma unroll
                for (int k = 0; k < 8; k++) {
                    if ((msk[k] >> l) & 1u) {
                        float a = __shfl_sync(0xffffffffu, al[k], l);
                        float wv = a * T[k];
                        acc[k*4+0] = fmaf(wv, col.x, acc[k*4+0]);
                        acc[k*4+1] = fmaf(wv, col.y, acc[k*4+1]);
                        acc[k*4+2] = fmaf(wv, col.z, acc[k*4+2]);
                        acc[k*4+3] = fmaf(wv, col.w, acc[k*4+3]);
                        T[k] *= (1.0f - a);
                    }
                }
            }
        }
    }

    #pragma unroll
    for (int k = 0; k < 8; k++) {
        int c = col0 + k;
        if (c < BEV_W) {
            int p = r*BEV_W + c;
            #pragma unroll
            for (int j = 0; j < 4; j++)
                out[(lane*4 + j)*P_TOT + p] = acc[k*4 + j];
        }
    }
}

__global__ void k_count(float* __restrict__ dst) {
    dst[0] = (float)g_cnt;
}

// ---------------- launch ----------------
extern "C" void kernel_launch(void* const* d_in, const int* in_sizes, int n_in,
                              void* d_out, int out_size) {
    const float* rots   = (const float*)d_in[0];
    const float* trans  = (const float*)d_in[1];
    const float* intr   = (const float*)d_in[2];
    const float* prots  = (const float*)d_in[3];
    const float* ptrans = (const float*)d_in[4];
    const float* feats  = (const float*)d_in[5];
    const float* c1w = (const float*)d_in[6];
    const float* c1b = (const float*)d_in[7];
    const float* g1  = (const float*)d_in[8];
    const float* b1  = (const float*)d_in[9];
    const float* m1  = (const float*)d_in[10];
    const float* v1  = (const float*)d_in[11];
    const float* c2w = (const float*)d_in[12];
    const float* c2b = (const float*)d_in[13];
    const float* g2  = (const float*)d_in[14];
    const float* b2  = (const float*)d_in[15];
    const float* m2  = (const float*)d_in[16];
    const float* v2  = (const float*)d_in[17];
    const float* c3w = (const float*)d_in[18];
    const float* c3b = (const float*)d_in[19];
    float* out = (float*)d_out;

    k_setup<<<1, 256>>>(rots, trans, intr, prots, ptrans,
                        c1b, g1, b1, m1, v1, c2b, g2, b2, m2, v2);
    k_wtrans<<<576, 256>>>(c1w, c2w);
    k_conv3g<<<dim3(44, 6), 256>>>(feats, 0);
    k_conv3g<<<dim3(44, 6), 256>>>(feats, 1);
    k_conv1x1<<<dim3(44, 3, 6), 256>>>(c3w, c3b);
    k_gauss<<<132, 128>>>();
    k_rows<<<BEV_H, 256>>>();
    k_splat2<<<BEV_H, 416>>>(out);
    if (out_size > P_TOT*OUTC)
        k_count<<<1, 1>>>(out + P_TOT*OUTC);
}

// round 8
// speedup vs baseline: 2.4202x; 1.7194x over previous
#include <cuda_runtime.h>

// ---------------- static config ----------------
#define NCAM   6
#define FC     128
#define FH     32
#define FW     88
#define NPIX   (FH*FW)          // 2816
#define DLEV   41
#define OC3    170              // 41 depth + 1 opacity + 128 feat
#define OUTC   128
#define G_TOT  (NCAM*NPIX)      // 16896
#define BEV_H  100
#define BEV_W  100
#define P_TOT  (BEV_H*BEV_W)    // 10000
#define KTOT   (9*FC)           // 1152
#define NSEG   4

// ---------------- scratch (device globals; no allocation) ----------------
__device__ float g_x1[NCAM*FC*NPIX];
__device__ float g_x2[NCAM*FC*NPIX];
__device__ float g_logits[NCAM*OC3*NPIX];
__device__ float g_colors[G_TOT*OUTC];
__device__ float g_wt1[KTOT*FC];
__device__ float g_wt2[KTOT*FC];
__device__ float4 g_pk0[G_TOT], g_pk1[G_TOT];
__device__ int   g_rmin[G_TOT], g_rmax[G_TOT];
__device__ int   g_list[BEV_H*G_TOT];
__device__ int   g_len[BEV_H];
__device__ float g_sacc[NSEG][P_TOT*OUTC];   // per-segment partial composites
__device__ float g_sT[NSEG][P_TOT];          // per-segment transmittance products
__device__ float g_cam[NCAM*24];
__device__ float g_sc1[FC], g_sh1[FC], g_sc2[FC], g_sh2[FC];
__device__ int   g_cnt;

// ---------------- setup ----------------
__device__ __forceinline__ void inv3(const float* m, float* o) {
    float a=m[0],b=m[1],c=m[2],d=m[3],e=m[4],f=m[5],g=m[6],h=m[7],i=m[8];
    float A =  (e*i - f*h);
    float B = -(d*i - f*g);
    float C =  (d*h - e*g);
    float det = a*A + b*B + c*C;
    float id = 1.0f/det;
    o[0]=A*id;            o[1]=-(b*i-c*h)*id;  o[2]= (b*f-c*e)*id;
    o[3]=B*id;            o[4]= (a*i-c*g)*id;  o[5]=-(a*f-c*d)*id;
    o[6]=C*id;            o[7]=-(a*h-b*g)*id;  o[8]= (a*e-b*d)*id;
}

__global__ void k_setup(const float* __restrict__ rots, const float* __restrict__ trans,
                        const float* __restrict__ intr, const float* __restrict__ prots,
                        const float* __restrict__ ptrans,
                        const float* __restrict__ c1b, const float* __restrict__ g1,
                        const float* __restrict__ b1,  const float* __restrict__ m1,
                        const float* __restrict__ v1,
                        const float* __restrict__ c2b, const float* __restrict__ g2,
                        const float* __restrict__ b2,  const float* __restrict__ m2,
                        const float* __restrict__ v2) {
    int t = threadIdx.x;
    if (t < NCAM) {
        float iK[9], iPR[9], comb[9];
        inv3(intr + t*9, iK);
        inv3(prots + t*9, iPR);
        const float* R = rots + t*9;
        #pragma unroll
        for (int r = 0; r < 3; r++)
            #pragma unroll
            for (int c = 0; c < 3; c++)
                comb[r*3+c] = R[r*3+0]*iK[0*3+c] + R[r*3+1]*iK[1*3+c] + R[r*3+2]*iK[2*3+c];
        float* o = g_cam + t*24;
        #pragma unroll
        for (int j = 0; j < 9; j++) o[j]   = comb[j];
        #pragma unroll
        for (int j = 0; j < 9; j++) o[9+j] = iPR[j];
        o[18]=trans[t*3+0]; o[19]=trans[t*3+1]; o[20]=trans[t*3+2];
        o[21]=ptrans[t*3+0]; o[22]=ptrans[t*3+1]; o[23]=ptrans[t*3+2];
    }
    if (t < FC) {
        float s1 = g1[t]*rsqrtf(v1[t] + 1e-3f);
        g_sc1[t] = s1;
        g_sh1[t] = (c1b[t] - m1[t])*s1 + b1[t];
        float s2 = g2[t]*rsqrtf(v2[t] + 1e-3f);
        g_sc2[t] = s2;
        g_sh2[t] = (c2b[t] - m2[t])*s2 + b2[t];
    }
    if (t == 0) g_cnt = 0;
}

// ---------------- weight transpose ----------------
__global__ void k_wtrans(const float* __restrict__ w1, const float* __restrict__ w2) {
    int i = blockIdx.x * 256 + threadIdx.x;
    int k  = i >> 7, oc = i & 127;
    int s  = k >> 7, ic = k & 127;
    int src = oc*KTOT + ic*9 + s;
    g_wt1[i] = w1[src];
    g_wt2[i] = w2[src];
}

// ---------------- conv3x3 as implicit GEMM ----------------
__global__ void k_conv3g(const float* __restrict__ feats, int layer) {
    __shared__ float sW[16][128];
    __shared__ float sX[16][64];
    const float* in_ = layer ? g_x1 : feats;
    const float* wt  = layer ? g_wt2 : g_wt1;
    float*       out = layer ? g_x2  : g_x1;
    const float* sc  = layer ? g_sc2 : g_sc1;
    const float* sh  = layer ? g_sh2 : g_sh1;

    int p0 = blockIdx.x * 64;
    int n  = blockIdx.y;
    int tid = threadIdx.x;
    int tx = tid & 15;
    int ty = tid >> 4;

    float acc[8][4];
    #pragma unroll
    for (int i = 0; i < 8; i++)
        #pragma unroll
        for (int j = 0; j < 4; j++) acc[i][j] = 0.0f;

    const float* inBase = in_ + n*FC*NPIX;

    // s-invariant staging coords
    int kkU[4], ppU[4], hU[4], wU[4];
    #pragma unroll
    for (int u = 0; u < 4; u++) {
        int e  = tid + u*256;
        kkU[u] = e >> 6; ppU[u] = e & 63;
        int p = p0 + ppU[u];
        hU[u] = p / FW; wU[u] = p - hU[u]*FW;
    }

    for (int s = 0; s < 9; s++) {
        int dh = s/3 - 1, dw = s%3 - 1;
        int doff = dh*FW + dw;
        bool valU[4]; int adrU[4];
        #pragma unroll
        for (int u = 0; u < 4; u++) {
            int hh = hU[u] + dh, ww = wU[u] + dw;
            valU[u] = ((unsigned)hh < FH) && ((unsigned)ww < FW);
            adrU[u] = p0 + ppU[u] + doff;
        }
        for (int ic0 = 0; ic0 < FC; ic0 += 16) {
            __syncthreads();
            {
                int k0 = s*FC + ic0;
                #pragma unroll
                for (int u = 0; u < 2; u++) {
                    int e  = tid + u*256;
                    int kk = e >> 5, cv = e & 31;
                    ((float4*)&sW[kk][0])[cv] = ((const float4*)&wt[(k0+kk)*FC])[cv];
                }
            }
            #pragma unroll
            for (int u = 0; u < 4; u++) {
                float v = valU[u] ? inBase[(ic0+kkU[u])*NPIX + adrU[u]] : 0.0f;
                sX[kkU[u]][ppU[u]] = v;
            }
            __syncthreads();
            #pragma unroll
            for (int kk = 0; kk < 16; kk++) {
                float4 xv = *(const float4*)&sX[kk][tx*4];
                float4 w0 = *(const float4*)&sW[kk][ty*8];
                float4 w1 = *(const float4*)&sW[kk][ty*8+4];
                float wv[8] = {w0.x,w0.y,w0.z,w0.w,w1.x,w1.y,w1.z,w1.w};
                float xr[4] = {xv.x,xv.y,xv.z,xv.w};
                #pragma unroll
                for (int i = 0; i < 8; i++)
                    #pragma unroll
                    for (int j = 0; j < 4; j++)
                        acc[i][j] = fmaf(wv[i], xr[j], acc[i][j]);
            }
        }
    }

    #pragma unroll
    for (int i = 0; i < 8; i++) {
        int oc = ty*8 + i;
        float scv = sc[oc], shv = sh[oc];
        float* op_ = out + (n*FC + oc)*NPIX + p0 + tx*4;
        #pragma unroll
        for (int j = 0; j < 4; j++)
            op_[j] = fmaxf(fmaf(acc[i][j], scv, shv), 0.0f);
    }
}

// ---------------- conv1x1 tiled GEMM ----------------
__global__ void k_conv1x1(const float* __restrict__ w3, const float* __restrict__ b3) {
    __shared__ float sW[16][64];
    __shared__ float sX[16][64];
    int p0  = blockIdx.x * 64;
    int oc0 = blockIdx.y * 64;
    int n   = blockIdx.z;
    int tid = threadIdx.x;
    int tx  = tid & 15;
    int ty  = tid >> 4;

    float acc[4][4];
    #pragma unroll
    for (int i = 0; i < 4; i++)
        #pragma unroll
        for (int j = 0; j < 4; j++) acc[i][j] = 0.0f;

    for (int k0 = 0; k0 < FC; k0 += 16) {
        #pragma unroll
        for (int i = tid; i < 16*64; i += 256) {
            int kk = i >> 6, oc = i & 63;
            int ocg = oc0 + oc;
            sW[kk][oc] = (ocg < OC3) ? w3[ocg*FC + k0 + kk] : 0.0f;
        }
        #pragma unroll
        for (int i = tid; i < 16*64; i += 256) {
            int kk = i >> 6, pp = i & 63;
            sX[kk][pp] = g_x2[(n*FC + k0 + kk)*NPIX + p0 + pp];
        }
        __syncthreads();
        #pragma unroll
        for (int kk = 0; kk < 16; kk++) {
            float xv[4], wv[4];
            #pragma unroll
            for (int j = 0; j < 4; j++) xv[j] = sX[kk][tx*4 + j];
            #pragma unroll
            for (int i = 0; i < 4; i++) wv[i] = sW[kk][ty*4 + i];
            #pragma unroll
            for (int i = 0; i < 4; i++)
                #pragma unroll
                for (int j = 0; j < 4; j++)
                    acc[i][j] = fmaf(wv[i], xv[j], acc[i][j]);
        }
        __syncthreads();
    }
    #pragma unroll
    for (int i = 0; i < 4; i++) {
        int oc = oc0 + ty*4 + i;
        if (oc < OC3) {
            float bb = __ldg(&b3[oc]);
            #pragma unroll
            for (int j = 0; j < 4; j++)
                g_logits[(n*OC3 + oc)*NPIX + p0 + tx*4 + j] = acc[i][j] + bb;
        }
    }
}

// ---------------- gaussian prep ----------------
__global__ void k_gauss() {
    int g = blockIdx.x * 128 + threadIdx.x;
    int n = g / NPIX;
    int p = g - n*NPIX;
    int h = p / FW;
    int w = p - h*FW;
    const float* L = g_logits + n*OC3*NPIX + p;

    float lg[DLEV];
    float mval = -1e30f;
    #pragma unroll
    for (int d = 0; d < DLEV; d++) { lg[d] = L[d*NPIX]; mval = fmaxf(mval, lg[d]); }
    float sum = 0.0f;
    #pragma unroll
    for (int d = 0; d < DLEV; d++) { lg[d] = __expf(lg[d] - mval); sum += lg[d]; }
    float inv = 1.0f / sum;

    const float* cm = g_cam + n*24;
    float c00=cm[0], c01=cm[1], c02=cm[2], c10=cm[3], c11=cm[4], c12=cm[5];
    float i00=cm[9], i01=cm[10], i02=cm[11], i10=cm[12], i11=cm[13], i12=cm[14];
    float i20=cm[15], i21=cm[16], i22=cm[17];
    float tx=cm[18], ty=cm[19];
    float ptx=cm[21], pty=cm[22], ptz=cm[23];
    float xs = (float)w * (703.0f/87.0f);
    float ys = (float)h * (255.0f/31.0f);
    float b0 = xs - ptx, b1 = ys - pty, b2 = -ptz;
    float bx = i00*b0 + i01*b1 + i02*b2;
    float by = i10*b0 + i11*b1 + i12*b2;
    float bz = i20*b0 + i21*b1 + i22*b2;
    float dx = i02, dy = i12, dz = i22;

    float mex = 0.0f, mey = 0.0f;
    #pragma unroll
    for (int d = 0; d < DLEV; d++) {
        float dep = 4.0f + (float)d;
        float p1x = bx + dep*dx, p1y = by + dep*dy, p1z = bz + dep*dz;
        float p2x = p1x*p1z, p2y = p1y*p1z;
        float gx = c00*p2x + c01*p2y + c02*p1z + tx;
        float gy = c10*p2x + c11*p2y + c12*p1z + ty;
        float pr = lg[d]*inv;
        mex += pr*gx; mey += pr*gy;
    }
    float cxx = 0.0f, cxy = 0.0f, cyy = 0.0f;
    #pragma unroll
    for (int d = 0; d < DLEV; d++) {
        float dep = 4.0f + (float)d;
        float p1x = bx + dep*dx, p1y = by + dep*dy, p1z = bz + dep*dz;
        float p2x = p1x*p1z, p2y = p1y*p1z;
        float gx = c00*p2x + c01*p2y + c02*p1z + tx;
        float gy = c10*p2x + c11*p2y + c12*p1z + ty;
        float ddx = mex - gx, ddy = mey - gy;
        float pr = lg[d]*inv;
        cxx += pr*ddx*ddx; cxy += pr*ddx*ddy; cyy += pr*ddy*ddy;
    }
    float a_ = cyy*(1.0f/9.0f) + 0.3f;
    float c_ = cxx*(1.0f/9.0f) + 0.3f;
    float b_ = cxy*(1.0f/9.0f);
    float det = a_*c_ - b_*b_;

    float opl = L[DLEV*NPIX];
    float op = 1.0f / (1.0f + __expf(-opl));
    bool msk = (op > 0.05f);
    if (msk) atomicAdd(&g_cnt, 1);
    bool valid = msk && (det > 0.0f);
    float idet = valid ? (1.0f/det) : 0.0f;

    float my = 50.0f - mey;
    float mx = 50.0f - mex;
    float qm = valid ? 2.0f*logf(255.0f*op) : -1e30f;

    g_pk0[g] = make_float4(my, mx, c_*idet, -b_*idet);
    g_pk1[g] = make_float4(a_*idet, op, qm, 0.0f);

    int r0 = 1, r1 = 0;
    if (valid) {
        float ext = sqrtf(fmaxf(qm, 0.0f)*a_) + 0.6f;
        r0 = max(0,  (int)ceilf(my - ext));
        r1 = min(99, (int)floorf(my + ext));
    }
    g_rmin[g] = r0;
    g_rmax[g] = r1;

    float4* cp4 = (float4*)(g_colors + g*OUTC);
    const float* fp_ = L + (DLEV+1)*NPIX;
    #pragma unroll
    for (int c = 0; c < OUTC; c += 4) {
        float4 v;
        v.x = fp_[(c+0)*NPIX];
        v.y = fp_[(c+1)*NPIX];
        v.z = fp_[(c+2)*NPIX];
        v.w = fp_[(c+3)*NPIX];
        cp4[c >> 2] = v;
    }
}

// ---------------- per-row ordered list build ----------------
__global__ void k_rows() {
    int r = blockIdx.x;
    int tid = threadIdx.x, lane = tid & 31, wid = tid >> 5;
    __shared__ int sCnt[8];
    __shared__ int sOff, sTot;
    if (tid == 0) sOff = 0;
    __syncthreads();
    for (int base = 0; base < G_TOT; base += 256) {
        int g = base + tid;
        bool f = (g_rmin[g] <= r) && (r <= g_rmax[g]);
        unsigned b = __ballot_sync(0xffffffffu, f);
        if (lane == 0) sCnt[wid] = __popc(b);
        __syncthreads();
        if (tid == 0) {
            int t = 0;
            #pragma unroll
            for (int i = 0; i < 8; i++) { int c = sCnt[i]; sCnt[i] = t; t += c; }
            sTot = t;
        }
        __syncthreads();
        if (f) {
            int pos = sOff + sCnt[wid] + __popc(b & ((1u << lane) - 1u));
            g_list[r*G_TOT + pos] = g;
        }
        __syncthreads();
        if (tid == 0) sOff += sTot;
        __syncthreads();
    }
    if (tid == 0) g_len[r] = sOff;
}

// ---------------- splat: segmented, scan-based compositing ----------------
// grid (100 rows, NSEG segments), block 416 = 13 warps x 8 px.
__global__ void k_splat3() {
    int r   = blockIdx.x;
    int seg = blockIdx.y;
    int warp = threadIdx.x >> 5;
    int lane = threadIdx.x & 31;
    int col0 = warp * 8;
    float fi = (float)r;

    float pj[8], T[8], acc[32];
    #pragma unroll
    for (int k = 0; k < 8; k++) {
        int c = col0 + k;
        pj[k] = (c < BEV_W) ? (float)c : 1e15f;
        T[k]  = (c < BEV_W) ? 1.0f : 0.0f;
    }
    #pragma unroll
    for (int j = 0; j < 32; j++) acc[j] = 0.0f;

    __shared__ int   sId[128];
    __shared__ float sP[128][9];

    int len = g_len[r];
    int s0 = (len * seg) / NSEG;
    int s1 = (len * (seg+1)) / NSEG;
    const int* lst = g_list + r*G_TOT;

    for (int c0 = s0; c0 < s1; c0 += 128) {
        __syncthreads();
        if (threadIdx.x < 128) {
            int idx = c0 + threadIdx.x;
            if (idx < s1) {
                int gid = lst[idx];
                sId[threadIdx.x] = gid;
                float4 a = g_pk0[gid];
                float4 b = g_pk1[gid];
                sP[threadIdx.x][0] = a.x; sP[threadIdx.x][1] = a.y;
                sP[threadIdx.x][2] = a.z; sP[threadIdx.x][3] = a.w;
                sP[threadIdx.x][4] = b.x; sP[threadIdx.x][5] = b.y;
                sP[threadIdx.x][6] = b.z;
            } else {
                sId[threadIdx.x] = 0;
                sP[threadIdx.x][0] = 0.0f; sP[threadIdx.x][1] = 0.0f;
                sP[threadIdx.x][2] = 0.0f; sP[threadIdx.x][3] = 0.0f;
                sP[threadIdx.x][4] = 0.0f; sP[threadIdx.x][5] = 0.0f;
                sP[threadIdx.x][6] = -1e30f;
            }
        }
        __syncthreads();

        float ts = 0.0f;
        #pragma unroll
        for (int k = 0; k < 8; k++) ts += T[k];
        if (ts < 1e-9f) continue;   // warp-uniform

        for (int sub = 0; sub < 128; sub += 32) {
            int gl = sub + lane;
            float my = sP[gl][0], mxx = sP[gl][1];
            float A  = sP[gl][2], Bc  = sP[gl][3], Cc = sP[gl][4];
            float op = sP[gl][5], qm  = sP[gl][6];

            float dI = fi - my;
            float c1 = A*dI*dI;
            float c2 = 2.0f*Bc*dI;

            float al[8]; unsigned msk[8];
            #pragma unroll
            for (int k = 0; k < 8; k++) {
                float dJ = pj[k] - mxx;
                float q = c1 + c2*dJ + Cc*dJ*dJ;
                float a_v = 0.0f;
                if (q >= 0.0f && q <= qm + 1e-3f) {
                    a_v = fminf(0.99f, op*__expf(-0.5f*q));
                    if (a_v < (1.0f/255.0f)) a_v = 0.0f;
                }
                al[k] = a_v;
                msk[k] = __ballot_sync(0xffffffffu, a_v > 0.0f);
            }
            unsigned un = msk[0] | msk[1] | msk[2] | msk[3]
                        | msk[4] | msk[5] | msk[6] | msk[7];
            if (!un) continue;

            // per-pixel warp multiplicative scan -> all 32 weights at once
            float wv[8];
            #pragma unroll
            for (int k = 0; k < 8; k++) {
                wv[k] = 0.0f;
                if (msk[k]) {                           // warp-uniform
                    float incl = 1.0f - al[k];
                    #pragma unroll
                    for (int off = 1; off < 32; off <<= 1) {
                        float u = __shfl_up_sync(0xffffffffu, incl, off);
                        if (lane >= off) incl *= u;
                    }
                    float excl = __shfl_up_sync(0xffffffffu, incl, 1);
                    if (lane == 0) excl = 1.0f;
                    wv[k] = al[k] * T[k] * excl;
                    T[k] *= __shfl_sync(0xffffffffu, incl, 31);
                }
            }

            // independent hit loop: no loop-carried deps -> loads pipeline
            while (un) {
                int l = __ffs(un) - 1;
                un &= un - 1;
                int gid = sId[sub + l];
                const float4 col = *(const float4*)(g_colors + gid*OUTC + lane*4);
                #pragma unroll
                for (int k = 0; k < 8; k++) {
                    if ((msk[k] >> l) & 1u) {           // warp-uniform
                        float wk = __shfl_sync(0xffffffffu, wv[k], l);
                        acc[k*4+0] = fmaf(wk, col.x, acc[k*4+0]);
                        acc[k*4+1] = fmaf(wk, col.y, acc[k*4+1]);
                        acc[k*4+2] = fmaf(wk, col.z, acc[k*4+2]);
                        acc[k*4+3] = fmaf(wk, col.w, acc[k*4+3]);
                    }
                }
            }
        }
    }

    #pragma unroll
    for (int k = 0; k < 8; k++) {
        int c = col0 + k;
        if (c < BEV_W) {
            int p = r*BEV_W + c;
            #pragma unroll
            for (int j = 0; j < 4; j++)
                g_sacc[seg][(lane*4 + j)*P_TOT + p] = acc[k*4 + j];
            if (lane == 0) g_sT[seg][p] = T[k];
        }
    }
}

// ---------------- combine segments: out = a0 + T0(a1 + T1(a2 + T2 a3)) --------
__global__ void k_combine(float* __restrict__ out) {
    int i = blockIdx.x * 256 + threadIdx.x;     // 5000 blocks, exact 1,280,000
    int p = i % P_TOT;
    float v = g_sacc[3][i];
    v = g_sacc[2][i] + g_sT[2][p] * v;
    v = g_sacc[1][i] + g_sT[1][p] * v;
    v = g_sacc[0][i] + g_sT[0][p] * v;
    out[i] = v;
}

__global__ void k_count(float* __restrict__ dst) {
    dst[0] = (float)g_cnt;
}

// ---------------- launch ----------------
extern "C" void kernel_launch(void* const* d_in, const int* in_sizes, int n_in,
                              void* d_out, int out_size) {
    const float* rots   = (const float*)d_in[0];
    const float* trans  = (const float*)d_in[1];
    const float* intr   = (const float*)d_in[2];
    const float* prots  = (const float*)d_in[3];
    const float* ptrans = (const float*)d_in[4];
    const float* feats  = (const float*)d_in[5];
    const float* c1w = (const float*)d_in[6];
    const float* c1b = (const float*)d_in[7];
    const float* g1  = (const float*)d_in[8];
    const float* b1  = (const float*)d_in[9];
    const float* m1  = (const float*)d_in[10];
    const float* v1  = (const float*)d_in[11];
    const float* c2w = (const float*)d_in[12];
    const float* c2b = (const float*)d_in[13];
    const float* g2  = (const float*)d_in[14];
    const float* b2  = (const float*)d_in[15];
    const float* m2  = (const float*)d_in[16];
    const float* v2  = (const float*)d_in[17];
    const float* c3w = (const float*)d_in[18];
    const float* c3b = (const float*)d_in[19];
    float* out = (float*)d_out;

    k_setup<<<1, 256>>>(rots, trans, intr, prots, ptrans,
                        c1b, g1, b1, m1, v1, c2b, g2, b2, m2, v2);
    k_wtrans<<<576, 256>>>(c1w, c2w);
    k_conv3g<<<dim3(44, 6), 256>>>(feats, 0);
    k_conv3g<<<dim3(44, 6), 256>>>(feats, 1);
    k_conv1x1<<<dim3(44, 3, 6), 256>>>(c3w, c3b);
    k_gauss<<<132, 128>>>();
    k_rows<<<BEV_H, 256>>>();
    k_splat3<<<dim3(BEV_H, NSEG), 416>>>();
    k_combine<<<5000, 256>>>(out);
    if (out_size > P_TOT*OUTC)
        k_count<<<1, 1>>>(out + P_TOT*OUTC);
}

// round 9
// speedup vs baseline: 3.3082x; 1.3669x over previous
#include <cuda_runtime.h>

// ---------------- static config ----------------
#define NCAM   6
#define FC     128
#define FH     32
#define FW     88
#define NPIX   (FH*FW)          // 2816
#define DLEV   41
#define OC3    170              // 41 depth + 1 opacity + 128 feat
#define OUTC   128
#define G_TOT  (NCAM*NPIX)      // 16896
#define BEV_H  100
#define BEV_W  100
#define P_TOT  (BEV_H*BEV_W)    // 10000
#define KTOT   (9*FC)           // 1152
#define NSEG   4

// ---------------- scratch (device globals; no allocation) ----------------
__device__ float g_x1[NCAM*FC*NPIX];
__device__ float g_x2[NCAM*FC*NPIX];
__device__ float g_logits[NCAM*OC3*NPIX];
__device__ float g_colors[G_TOT*OUTC];
__device__ float g_wt1[KTOT*FC];
__device__ float g_wt2[KTOT*FC];
__device__ float4 g_pk0[G_TOT], g_pk1[G_TOT];
__device__ int   g_rmin[G_TOT], g_rmax[G_TOT];
__device__ int   g_list[BEV_H*G_TOT];
__device__ int   g_len[BEV_H];
__device__ float g_sacc[NSEG][P_TOT*OUTC];
__device__ float g_sT[NSEG][P_TOT];
__device__ float g_cam[NCAM*24];
__device__ float g_sc1[FC], g_sh1[FC], g_sc2[FC], g_sh2[FC];
__device__ int   g_cnt;

// ---------------- setup ----------------
__device__ __forceinline__ void inv3(const float* m, float* o) {
    float a=m[0],b=m[1],c=m[2],d=m[3],e=m[4],f=m[5],g=m[6],h=m[7],i=m[8];
    float A =  (e*i - f*h);
    float B = -(d*i - f*g);
    float C =  (d*h - e*g);
    float det = a*A + b*B + c*C;
    float id = 1.0f/det;
    o[0]=A*id;            o[1]=-(b*i-c*h)*id;  o[2]= (b*f-c*e)*id;
    o[3]=B*id;            o[4]= (a*i-c*g)*id;  o[5]=-(a*f-c*d)*id;
    o[6]=C*id;            o[7]=-(a*h-b*g)*id;  o[8]= (a*e-b*d)*id;
}

__global__ void k_setup(const float* __restrict__ rots, const float* __restrict__ trans,
                        const float* __restrict__ intr, const float* __restrict__ prots,
                        const float* __restrict__ ptrans,
                        const float* __restrict__ c1b, const float* __restrict__ g1,
                        const float* __restrict__ b1,  const float* __restrict__ m1,
                        const float* __restrict__ v1,
                        const float* __restrict__ c2b, const float* __restrict__ g2,
                        const float* __restrict__ b2,  const float* __restrict__ m2,
                        const float* __restrict__ v2) {
    int t = threadIdx.x;
    if (t < NCAM) {
        float iK[9], iPR[9], comb[9];
        inv3(intr + t*9, iK);
        inv3(prots + t*9, iPR);
        const float* R = rots + t*9;
        #pragma unroll
        for (int r = 0; r < 3; r++)
            #pragma unroll
            for (int c = 0; c < 3; c++)
                comb[r*3+c] = R[r*3+0]*iK[0*3+c] + R[r*3+1]*iK[1*3+c] + R[r*3+2]*iK[2*3+c];
        float* o = g_cam + t*24;
        #pragma unroll
        for (int j = 0; j < 9; j++) o[j]   = comb[j];
        #pragma unroll
        for (int j = 0; j < 9; j++) o[9+j] = iPR[j];
        o[18]=trans[t*3+0]; o[19]=trans[t*3+1]; o[20]=trans[t*3+2];
        o[21]=ptrans[t*3+0]; o[22]=ptrans[t*3+1]; o[23]=ptrans[t*3+2];
    }
    if (t < FC) {
        float s1 = g1[t]*rsqrtf(v1[t] + 1e-3f);
        g_sc1[t] = s1;
        g_sh1[t] = (c1b[t] - m1[t])*s1 + b1[t];
        float s2 = g2[t]*rsqrtf(v2[t] + 1e-3f);
        g_sc2[t] = s2;
        g_sh2[t] = (c2b[t] - m2[t])*s2 + b2[t];
    }
    if (t == 0) g_cnt = 0;
}

// ---------------- weight transpose ----------------
__global__ void k_wtrans(const float* __restrict__ w1, const float* __restrict__ w2) {
    int i = blockIdx.x * 256 + threadIdx.x;
    int k  = i >> 7, oc = i & 127;
    int s  = k >> 7, ic = k & 127;
    int src = oc*KTOT + ic*9 + s;
    g_wt1[i] = w1[src];
    g_wt2[i] = w2[src];
}

// ---------------- conv3x3 as implicit GEMM ----------------
__global__ void k_conv3g(const float* __restrict__ feats, int layer) {
    __shared__ float sW[16][128];
    __shared__ float sX[16][64];
    const float* in_ = layer ? g_x1 : feats;
    const float* wt  = layer ? g_wt2 : g_wt1;
    float*       out = layer ? g_x2  : g_x1;
    const float* sc  = layer ? g_sc2 : g_sc1;
    const float* sh  = layer ? g_sh2 : g_sh1;

    int p0 = blockIdx.x * 64;
    int n  = blockIdx.y;
    int tid = threadIdx.x;
    int tx = tid & 15;
    int ty = tid >> 4;

    float acc[8][4];
    #pragma unroll
    for (int i = 0; i < 8; i++)
        #pragma unroll
        for (int j = 0; j < 4; j++) acc[i][j] = 0.0f;

    const float* inBase = in_ + n*FC*NPIX;

    int kkU[4], ppU[4], hU[4], wU[4];
    #pragma unroll
    for (int u = 0; u < 4; u++) {
        int e  = tid + u*256;
        kkU[u] = e >> 6; ppU[u] = e & 63;
        int p = p0 + ppU[u];
        hU[u] = p / FW; wU[u] = p - hU[u]*FW;
    }

    for (int s = 0; s < 9; s++) {
        int dh = s/3 - 1, dw = s%3 - 1;
        int doff = dh*FW + dw;
        bool valU[4]; int adrU[4];
        #pragma unroll
        for (int u = 0; u < 4; u++) {
            int hh = hU[u] + dh, ww = wU[u] + dw;
            valU[u] = ((unsigned)hh < FH) && ((unsigned)ww < FW);
            adrU[u] = p0 + ppU[u] + doff;
        }
        for (int ic0 = 0; ic0 < FC; ic0 += 16) {
            __syncthreads();
            {
                int k0 = s*FC + ic0;
                #pragma unroll
                for (int u = 0; u < 2; u++) {
                    int e  = tid + u*256;
                    int kk = e >> 5, cv = e & 31;
                    ((float4*)&sW[kk][0])[cv] = ((const float4*)&wt[(k0+kk)*FC])[cv];
                }
            }
            #pragma unroll
            for (int u = 0; u < 4; u++) {
                float v = valU[u] ? inBase[(ic0+kkU[u])*NPIX + adrU[u]] : 0.0f;
                sX[kkU[u]][ppU[u]] = v;
            }
            __syncthreads();
            #pragma unroll
            for (int kk = 0; kk < 16; kk++) {
                float4 xv = *(const float4*)&sX[kk][tx*4];
                float4 w0 = *(const float4*)&sW[kk][ty*8];
                float4 w1 = *(const float4*)&sW[kk][ty*8+4];
                float wv[8] = {w0.x,w0.y,w0.z,w0.w,w1.x,w1.y,w1.z,w1.w};
                float xr[4] = {xv.x,xv.y,xv.z,xv.w};
                #pragma unroll
                for (int i = 0; i < 8; i++)
                    #pragma unroll
                    for (int j = 0; j < 4; j++)
                        acc[i][j] = fmaf(wv[i], xr[j], acc[i][j]);
            }
        }
    }

    #pragma unroll
    for (int i = 0; i < 8; i++) {
        int oc = ty*8 + i;
        float scv = sc[oc], shv = sh[oc];
        float* op_ = out + (n*FC + oc)*NPIX + p0 + tx*4;
        #pragma unroll
        for (int j = 0; j < 4; j++)
            op_[j] = fmaxf(fmaf(acc[i][j], scv, shv), 0.0f);
    }
}

// ---------------- conv1x1 tiled GEMM ----------------
__global__ void k_conv1x1(const float* __restrict__ w3, const float* __restrict__ b3) {
    __shared__ float sW[16][64];
    __shared__ float sX[16][64];
    int p0  = blockIdx.x * 64;
    int oc0 = blockIdx.y * 64;
    int n   = blockIdx.z;
    int tid = threadIdx.x;
    int tx  = tid & 15;
    int ty  = tid >> 4;

    float acc[4][4];
    #pragma unroll
    for (int i = 0; i < 4; i++)
        #pragma unroll
        for (int j = 0; j < 4; j++) acc[i][j] = 0.0f;

    for (int k0 = 0; k0 < FC; k0 += 16) {
        #pragma unroll
        for (int i = tid; i < 16*64; i += 256) {
            int kk = i >> 6, oc = i & 63;
            int ocg = oc0 + oc;
            sW[kk][oc] = (ocg < OC3) ? w3[ocg*FC + k0 + kk] : 0.0f;
        }
        #pragma unroll
        for (int i = tid; i < 16*64; i += 256) {
            int kk = i >> 6, pp = i & 63;
            sX[kk][pp] = g_x2[(n*FC + k0 + kk)*NPIX + p0 + pp];
        }
        __syncthreads();
        #pragma unroll
        for (int kk = 0; kk < 16; kk++) {
            float xv[4], wv[4];
            #pragma unroll
            for (int j = 0; j < 4; j++) xv[j] = sX[kk][tx*4 + j];
            #pragma unroll
            for (int i = 0; i < 4; i++) wv[i] = sW[kk][ty*4 + i];
            #pragma unroll
            for (int i = 0; i < 4; i++)
                #pragma unroll
                for (int j = 0; j < 4; j++)
                    acc[i][j] = fmaf(wv[i], xv[j], acc[i][j]);
        }
        __syncthreads();
    }
    #pragma unroll
    for (int i = 0; i < 4; i++) {
        int oc = oc0 + ty*4 + i;
        if (oc < OC3) {
            float bb = __ldg(&b3[oc]);
            #pragma unroll
            for (int j = 0; j < 4; j++)
                g_logits[(n*OC3 + oc)*NPIX + p0 + tx*4 + j] = acc[i][j] + bb;
        }
    }
}

// ---------------- gaussian prep ----------------
__global__ void k_gauss() {
    int g = blockIdx.x * 128 + threadIdx.x;
    int n = g / NPIX;
    int p = g - n*NPIX;
    int h = p / FW;
    int w = p - h*FW;
    const float* L = g_logits + n*OC3*NPIX + p;

    float lg[DLEV];
    float mval = -1e30f;
    #pragma unroll
    for (int d = 0; d < DLEV; d++) { lg[d] = L[d*NPIX]; mval = fmaxf(mval, lg[d]); }
    float sum = 0.0f;
    #pragma unroll
    for (int d = 0; d < DLEV; d++) { lg[d] = __expf(lg[d] - mval); sum += lg[d]; }
    float inv = 1.0f / sum;

    const float* cm = g_cam + n*24;
    float c00=cm[0], c01=cm[1], c02=cm[2], c10=cm[3], c11=cm[4], c12=cm[5];
    float i00=cm[9], i01=cm[10], i02=cm[11], i10=cm[12], i11=cm[13], i12=cm[14];
    float i20=cm[15], i21=cm[16], i22=cm[17];
    float tx=cm[18], ty=cm[19];
    float ptx=cm[21], pty=cm[22], ptz=cm[23];
    float xs = (float)w * (703.0f/87.0f);
    float ys = (float)h * (255.0f/31.0f);
    float b0 = xs - ptx, b1 = ys - pty, b2 = -ptz;
    float bx = i00*b0 + i01*b1 + i02*b2;
    float by = i10*b0 + i11*b1 + i12*b2;
    float bz = i20*b0 + i21*b1 + i22*b2;
    float dx = i02, dy = i12, dz = i22;

    float mex = 0.0f, mey = 0.0f;
    #pragma unroll
    for (int d = 0; d < DLEV; d++) {
        float dep = 4.0f + (float)d;
        float p1x = bx + dep*dx, p1y = by + dep*dy, p1z = bz + dep*dz;
        float p2x = p1x*p1z, p2y = p1y*p1z;
        float gx = c00*p2x + c01*p2y + c02*p1z + tx;
        float gy = c10*p2x + c11*p2y + c12*p1z + ty;
        float pr = lg[d]*inv;
        mex += pr*gx; mey += pr*gy;
    }
    float cxx = 0.0f, cxy = 0.0f, cyy = 0.0f;
    #pragma unroll
    for (int d = 0; d < DLEV; d++) {
        float dep = 4.0f + (float)d;
        float p1x = bx + dep*dx, p1y = by + dep*dy, p1z = bz + dep*dz;
        float p2x = p1x*p1z, p2y = p1y*p1z;
        float gx = c00*p2x + c01*p2y + c02*p1z + tx;
        float gy = c10*p2x + c11*p2y + c12*p1z + ty;
        float ddx = mex - gx, ddy = mey - gy;
        float pr = lg[d]*inv;
        cxx += pr*ddx*ddx; cxy += pr*ddx*ddy; cyy += pr*ddy*ddy;
    }
    float a_ = cyy*(1.0f/9.0f) + 0.3f;
    float c_ = cxx*(1.0f/9.0f) + 0.3f;
    float b_ = cxy*(1.0f/9.0f);
    float det = a_*c_ - b_*b_;

    float opl = L[DLEV*NPIX];
    float op = 1.0f / (1.0f + __expf(-opl));
    bool msk = (op > 0.05f);
    if (msk) atomicAdd(&g_cnt, 1);
    bool valid = msk && (det > 0.0f);
    float idet = valid ? (1.0f/det) : 0.0f;

    float my = 50.0f - mey;
    float mx = 50.0f - mex;
    float qm = valid ? 2.0f*logf(255.0f*op) : -1e30f;

    g_pk0[g] = make_float4(my, mx, c_*idet, -b_*idet);
    g_pk1[g] = make_float4(a_*idet, op, qm, 0.0f);

    int r0 = 1, r1 = 0;
    if (valid) {
        float ext = sqrtf(fmaxf(qm, 0.0f)*a_) + 0.6f;
        r0 = max(0,  (int)ceilf(my - ext));
        r1 = min(99, (int)floorf(my + ext));
    }
    g_rmin[g] = r0;
    g_rmax[g] = r1;

    float4* cp4 = (float4*)(g_colors + g*OUTC);
    const float* fp_ = L + (DLEV+1)*NPIX;
    #pragma unroll
    for (int c = 0; c < OUTC; c += 4) {
        float4 v;
        v.x = fp_[(c+0)*NPIX];
        v.y = fp_[(c+1)*NPIX];
        v.z = fp_[(c+2)*NPIX];
        v.w = fp_[(c+3)*NPIX];
        cp4[c >> 2] = v;
    }
}

// ---------------- per-row ordered list build ----------------
__global__ void k_rows() {
    int r = blockIdx.x;
    int tid = threadIdx.x, lane = tid & 31, wid = tid >> 5;
    __shared__ int sCnt[8];
    __shared__ int sOff, sTot;
    if (tid == 0) sOff = 0;
    __syncthreads();
    for (int base = 0; base < G_TOT; base += 256) {
        int g = base + tid;
        bool f = (g_rmin[g] <= r) && (r <= g_rmax[g]);
        unsigned b = __ballot_sync(0xffffffffu, f);
        if (lane == 0) sCnt[wid] = __popc(b);
        __syncthreads();
        if (tid == 0) {
            int t = 0;
            #pragma unroll
            for (int i = 0; i < 8; i++) { int c = sCnt[i]; sCnt[i] = t; t += c; }
            sTot = t;
        }
        __syncthreads();
        if (f) {
            int pos = sOff + sCnt[wid] + __popc(b & ((1u << lane) - 1u));
            g_list[r*G_TOT + pos] = g;
        }
        __syncthreads();
        if (tid == 0) sOff += sTot;
        __syncthreads();
    }
    if (tid == 0) g_len[r] = sOff;
}

// ---------------- splat: scan weights -> smem, block-level color GEMM ----------
// grid (100 rows, NSEG), block 416 = 13 warps. Phase A: warp w owns px 8w..8w+7,
// lane = gaussian. Phase B: thread t owns px=t%104, channel quads tq+4j (tq=t/104).
__global__ void k_splat4() {
    int r   = blockIdx.x;
    int seg = blockIdx.y;
    int tid  = threadIdx.x;
    int warp = tid >> 5;
    int lane = tid & 31;
    int col0 = warp * 8;
    float fi = (float)r;

    int px = tid % 104;
    int tq = tid / 104;          // 0..3

    float pj[8], T[8];
    #pragma unroll
    for (int k = 0; k < 8; k++) {
        int c = col0 + k;
        pj[k] = (c < BEV_W) ? (float)c : 1e15f;
        T[k]  = 1.0f;
    }
    float acc[8][4];
    #pragma unroll
    for (int j = 0; j < 8; j++)
        #pragma unroll
        for (int jj = 0; jj < 4; jj++) acc[j][jj] = 0.0f;

    __shared__ int   sGid[32];
    __shared__ float sP[32][8];
    __shared__ float wBuf[32][105];     // pitch 105: conflict-free
    __shared__ float cBuf[32][128];

    int len = g_len[r];
    int s0 = (len * seg) / NSEG;
    int s1 = (len * (seg+1)) / NSEG;
    const int* lst = g_list + r*G_TOT;

    for (int c0 = s0; c0 < s1; c0 += 32) {
        __syncthreads();
        if (tid < 32) {
            int idx = c0 + tid;
            if (idx < s1) {
                int gid = lst[idx];
                sGid[tid] = gid;
                float4 a = g_pk0[gid];
                float4 b = g_pk1[gid];
                sP[tid][0] = a.x; sP[tid][1] = a.y;
                sP[tid][2] = a.z; sP[tid][3] = a.w;
                sP[tid][4] = b.x; sP[tid][5] = b.y;
                sP[tid][6] = b.z;
            } else {
                sGid[tid] = 0;
                sP[tid][0] = 0.0f; sP[tid][1] = 0.0f;
                sP[tid][2] = 0.0f; sP[tid][3] = 0.0f;
                sP[tid][4] = 0.0f; sP[tid][5] = 0.0f;
                sP[tid][6] = -1e30f;
            }
        }
        __syncthreads();
        // stage colors: 32 gaussians x 128 ch = 1024 float4
        for (int i = tid; i < 1024; i += 416) {
            int g = i >> 5, cv = i & 31;
            *(float4*)&cBuf[g][cv*4] = *(const float4*)(g_colors + sGid[g]*OUTC + cv*4);
        }

        // ---- phase A: weights via ordered multiplicative scan ----
        float my = sP[lane][0], mxx = sP[lane][1];
        float A  = sP[lane][2], Bc  = sP[lane][3], Cc = sP[lane][4];
        float op = sP[lane][5], qm  = sP[lane][6];
        float dI = fi - my;
        float c1 = A*dI*dI;
        float c2 = 2.0f*Bc*dI;

        float al[8]; unsigned msk[8];
        #pragma unroll
        for (int k = 0; k < 8; k++) {
            float dJ = pj[k] - mxx;
            float q = c1 + c2*dJ + Cc*dJ*dJ;
            float a_v = 0.0f;
            if (q >= 0.0f && q <= qm + 1e-3f) {
                a_v = fminf(0.99f, op*__expf(-0.5f*q));
                if (a_v < (1.0f/255.0f)) a_v = 0.0f;
            }
            al[k] = a_v;
            msk[k] = __ballot_sync(0xffffffffu, a_v > 0.0f);
        }
        #pragma unroll
        for (int k = 0; k < 8; k++) {
            float wv = 0.0f;
            if (msk[k]) {                         // warp-uniform
                float incl = 1.0f - al[k];
                #pragma unroll
                for (int off = 1; off < 32; off <<= 1) {
                    float u = __shfl_up_sync(0xffffffffu, incl, off);
                    if (lane >= off) incl *= u;
                }
                float excl = __shfl_up_sync(0xffffffffu, incl, 1);
                if (lane == 0) excl = 1.0f;
                wv = al[k] * T[k] * excl;
                T[k] *= __shfl_sync(0xffffffffu, incl, 31);
            }
            wBuf[lane][col0 + k] = wv;
        }
        __syncthreads();

        // ---- phase B: acc[px][cq] += sum_g w[g][px] * col[g][cq] ----
        #pragma unroll 4
        for (int g = 0; g < 32; g++) {
            float w = wBuf[g][px];
            if (__ballot_sync(0xffffffffu, w != 0.0f)) {
                #pragma unroll
                for (int j = 0; j < 8; j++) {
                    float4 col = *(const float4*)&cBuf[g][tq*4 + j*16];
                    acc[j][0] = fmaf(w, col.x, acc[j][0]);
                    acc[j][1] = fmaf(w, col.y, acc[j][1]);
                    acc[j][2] = fmaf(w, col.z, acc[j][2]);
                    acc[j][3] = fmaf(w, col.w, acc[j][3]);
                }
            }
        }
    }

    // store partial composite + transmittance
    if (px < BEV_W) {
        int p = r*BEV_W + px;
        #pragma unroll
        for (int j = 0; j < 8; j++) {
            int cq = tq + 4*j;
            #pragma unroll
            for (int jj = 0; jj < 4; jj++)
                g_sacc[seg][(cq*4 + jj)*P_TOT + p] = acc[j][jj];
        }
    }
    if (lane == 0) {
        #pragma unroll
        for (int k = 0; k < 8; k++) {
            int c = col0 + k;
            if (c < BEV_W) g_sT[seg][r*BEV_W + c] = T[k];
        }
    }
}

// ---------------- combine segments ----------------
__global__ void k_combine(float* __restrict__ out) {
    int i = blockIdx.x * 256 + threadIdx.x;
    int p = i % P_TOT;
    float v = g_sacc[3][i];
    v = g_sacc[2][i] + g_sT[2][p] * v;
    v = g_sacc[1][i] + g_sT[1][p] * v;
    v = g_sacc[0][i] + g_sT[0][p] * v;
    out[i] = v;
}

__global__ void k_count(float* __restrict__ dst) {
    dst[0] = (float)g_cnt;
}

// ---------------- launch ----------------
extern "C" void kernel_launch(void* const* d_in, const int* in_sizes, int n_in,
                              void* d_out, int out_size) {
    const float* rots   = (const float*)d_in[0];
    const float* trans  = (const float*)d_in[1];
    const float* intr   = (const float*)d_in[2];
    const float* prots  = (const float*)d_in[3];
    const float* ptrans = (const float*)d_in[4];
    const float* feats  = (const float*)d_in[5];
    const float* c1w = (const float*)d_in[6];
    const float* c1b = (const float*)d_in[7];
    const float* g1  = (const float*)d_in[8];
    const float* b1  = (const float*)d_in[9];
    const float* m1  = (const float*)d_in[10];
    const float* v1  = (const float*)d_in[11];
    const float* c2w = (const float*)d_in[12];
    const float* c2b = (const float*)d_in[13];
    const float* g2  = (const float*)d_in[14];
    const float* b2  = (const float*)d_in[15];
    const float* m2  = (const float*)d_in[16];
    const float* v2  = (const float*)d_in[17];
    const float* c3w = (const float*)d_in[18];
    const float* c3b = (const float*)d_in[19];
    float* out = (float*)d_out;

    k_setup<<<1, 256>>>(rots, trans, intr, prots, ptrans,
                        c1b, g1, b1, m1, v1, c2b, g2, b2, m2, v2);
    k_wtrans<<<576, 256>>>(c1w, c2w);
    k_conv3g<<<dim3(44, 6), 256>>>(feats, 0);
    k_conv3g<<<dim3(44, 6), 256>>>(feats, 1);
    k_conv1x1<<<dim3(44, 3, 6), 256>>>(c3w, c3b);
    k_gauss<<<132, 128>>>();
    k_rows<<<BEV_H, 256>>>();
    k_splat4<<<dim3(BEV_H, NSEG), 416>>>();
    k_combine<<<5000, 256>>>(out);
    if (out_size > P_TOT*OUTC)
        k_count<<<1, 1>>>(out + P_TOT*OUTC);
}